// round 10
// baseline (speedup 1.0000x reference)
#include <cuda_runtime.h>
#include <cuda_bf16.h>
#include <cuda_fp16.h>
#include <cstdint>

#define B_  2
#define S_  2048
#define D_  1024
#define H_  16
#define HD_ 64
#define M_  (B_*S_)   // 4096

// ---------------------------------------------------------------------------
// Scratch (allocation-free rule: static device globals)
// ---------------------------------------------------------------------------
__device__ __half g_xh16[M_*D_];              // fp16(x)
__device__ __half g_oh16[M_*D_];              // fp16(attention out)
__device__ __half g_wth[4][D_*D_], g_wtl[4][D_*D_];  // W^T split fp16 [N,K]

// split-bf16 q/k/v for tensor attention (written by QKV GEMM epilogue)
__device__ __nv_bfloat16 g_qh[M_*D_], g_ql[M_*D_];
__device__ __nv_bfloat16 g_kh[M_*D_], g_kl[M_*D_];
__device__ __nv_bfloat16 g_vh[M_*D_], g_vl[M_*D_];

// ---------------------------------------------------------------------------
__device__ __forceinline__ uint32_t smem_u32(const void* p) {
    uint32_t a;
    asm("{ .reg .u64 t; cvta.to.shared.u64 t, %1; cvt.u32.u64 %0, t; }" : "=r"(a) : "l"(p));
    return a;
}

#define CP_ASYNC16(dst, src) \
    asm volatile("cp.async.cg.shared.global [%0], [%1], 16;" :: "r"(dst), "l"(src))
#define CP_COMMIT()  asm volatile("cp.async.commit_group;" ::: "memory")
#define CP_WAIT(n)   asm volatile("cp.async.wait_group %0;" :: "n"(n) : "memory")

#define LDSM_X4(r0, r1, r2, r3, addr) \
    asm volatile("ldmatrix.sync.aligned.m8n8.x4.shared.b16 {%0,%1,%2,%3}, [%4];" \
        : "=r"(r0), "=r"(r1), "=r"(r2), "=r"(r3) : "r"(addr))

#define LDSM_X4T(r0, r1, r2, r3, addr) \
    asm volatile("ldmatrix.sync.aligned.m8n8.x4.trans.shared.b16 {%0,%1,%2,%3}, [%4];" \
        : "=r"(r0), "=r"(r1), "=r"(r2), "=r"(r3) : "r"(addr))

#define MMA_BF16(d, a, b) \
    asm volatile("mma.sync.aligned.m16n8k16.row.col.f32.bf16.bf16.f32 " \
        "{%0,%1,%2,%3}, {%4,%5,%6,%7}, {%8,%9}, {%0,%1,%2,%3};" \
        : "+f"((d)[0]), "+f"((d)[1]), "+f"((d)[2]), "+f"((d)[3]) \
        : "r"((a)[0]), "r"((a)[1]), "r"((a)[2]), "r"((a)[3]), "r"((b)[0]), "r"((b)[1]))

#define MMA_F16(d, a, b) \
    asm volatile("mma.sync.aligned.m16n8k16.row.col.f32.f16.f16.f32 " \
        "{%0,%1,%2,%3}, {%4,%5,%6,%7}, {%8,%9}, {%0,%1,%2,%3};" \
        : "+f"((d)[0]), "+f"((d)[1]), "+f"((d)[2]), "+f"((d)[3]) \
        : "r"((a)[0]), "r"((a)[1]), "r"((a)[2]), "r"((a)[3]), "r"((b)[0]), "r"((b)[1]))

__device__ __forceinline__ uint32_t pack_bf16x2(float lo, float hi) {
    uint32_t r;
    asm("cvt.rn.bf16x2.f32 %0, %1, %2;" : "=r"(r) : "f"(hi), "f"(lo));
    return r;
}
__device__ __forceinline__ float lo_f(uint32_t p) {
    __nv_bfloat162 v = *(__nv_bfloat162*)&p; return __bfloat162float(v.x);
}
__device__ __forceinline__ float hi_f(uint32_t p) {
    __nv_bfloat162 v = *(__nv_bfloat162*)&p; return __bfloat162float(v.y);
}

// split two fp32 into (hi bf16x2, lo bf16x2)
__device__ __forceinline__ void split2(float x, float y, uint32_t& hi, uint32_t& lo) {
    hi = pack_bf16x2(x, y);
    lo = pack_bf16x2(x - lo_f(hi), y - hi_f(hi));
}

// ---------------------------------------------------------------------------
// Convert fp32 x -> fp16 g_xh16.
// ---------------------------------------------------------------------------
__global__ void __launch_bounds__(256) convert_h(const float4* __restrict__ xin)
{
    const int i = blockIdx.x * 256 + threadIdx.x;
    const float4 v = xin[i];
    __half2 p0 = __floats2half2_rn(v.x, v.y);
    __half2 p1 = __floats2half2_rn(v.z, v.w);
    uint2 u; u.x = *(uint32_t*)&p0; u.y = *(uint32_t*)&p1;
    ((uint2*)g_xh16)[i] = u;
}

// ---------------------------------------------------------------------------
// Transpose + split: W[K,N] fp32 -> Wt[N,K] (hi,lo) fp16. z selects Wq/Wk/Wv/Wo.
// ---------------------------------------------------------------------------
__global__ void __launch_bounds__(256) transpose_split(
    const float* __restrict__ Wq, const float* __restrict__ Wk,
    const float* __restrict__ Wv, const float* __restrict__ Wo)
{
    const float* W = (blockIdx.z == 0) ? Wq : (blockIdx.z == 1) ? Wk
                   : (blockIdx.z == 2) ? Wv : Wo;
    __half* Thi = g_wth[blockIdx.z];
    __half* Tlo = g_wtl[blockIdx.z];

    __shared__ float tile[32][33];
    const int tx = threadIdx.x, ty = threadIdx.y;
    const int k0 = blockIdx.x * 32, n0 = blockIdx.y * 32;

    #pragma unroll
    for (int j = 0; j < 32; j += 8)
        tile[ty + j][tx] = W[(size_t)(k0 + ty + j) * D_ + n0 + tx];
    __syncthreads();
    #pragma unroll
    for (int j = 0; j < 32; j += 8) {
        float v = tile[tx][ty + j];
        __half h = __float2half(v);
        __half l = __float2half(v - __half2float(h));
        const size_t idx = (size_t)(n0 + ty + j) * D_ + k0 + tx;
        Thi[idx] = h;
        Tlo[idx] = l;
    }
}

// ---------------------------------------------------------------------------
// 2-pass split-fp16 GEMM (UNCHANGED from R9).
// ---------------------------------------------------------------------------
#define BK_   32
#define NT_   (D_ / BK_)
#define ROWE_ 40
#define TILE_BYTES (128 * ROWE_ * 2)
#define STAGE_BYTES (3 * TILE_BYTES)
#define GSMEM_BYTES (2 * STAGE_BYTES)

extern __shared__ char dsm[];

__global__ void __launch_bounds__(256, 2) mma_gemm(int mode,
    const float* __restrict__ b0, const float* __restrict__ b1,
    const float* __restrict__ b2, float* __restrict__ dout)
{
    const int z = mode ? 3 : blockIdx.z;
    const __half* A   = mode ? g_oh16 : g_xh16;
    const __half* Bh  = g_wth[z];
    const __half* Bl  = g_wtl[z];
    const float* bias = mode ? b0 : (z == 0 ? b0 : (z == 1 ? b1 : b2));

    const int tid  = threadIdx.x;
    const int lane = tid & 31;
    const int wid  = tid >> 5;
    const int wm   = (wid & 1) * 64;
    const int wn   = (wid >> 1) * 32;
    const int m0 = blockIdx.y * 128;
    const int n0 = blockIdx.x * 128;

    const uint32_t sb = smem_u32(dsm);

    const int cA = tid * 2, cB = tid * 2 + 1;
    const int rA = cA >> 2, qA = cA & 3;
    const int rB = cB >> 2, qB = cB & 3;

    auto issue = [&](int t) {
        const int kc = t * BK_;
        const uint32_t st = sb + (t & 1) * STAGE_BYTES;
        CP_ASYNC16(st + rA * 80 + qA * 16, A  + (size_t)(m0 + rA) * D_ + kc + qA * 8);
        CP_ASYNC16(st + rB * 80 + qB * 16, A  + (size_t)(m0 + rB) * D_ + kc + qB * 8);
        CP_ASYNC16(st + TILE_BYTES   + rA * 80 + qA * 16, Bh + (size_t)(n0 + rA) * D_ + kc + qA * 8);
        CP_ASYNC16(st + TILE_BYTES   + rB * 80 + qB * 16, Bh + (size_t)(n0 + rB) * D_ + kc + qB * 8);
        CP_ASYNC16(st + 2*TILE_BYTES + rA * 80 + qA * 16, Bl + (size_t)(n0 + rA) * D_ + kc + qA * 8);
        CP_ASYNC16(st + 2*TILE_BYTES + rB * 80 + qB * 16, Bl + (size_t)(n0 + rB) * D_ + kc + qB * 8);
        CP_COMMIT();
    };

    float d[4][4][4];
    #pragma unroll
    for (int i = 0; i < 4; ++i)
        #pragma unroll
        for (int j = 0; j < 4; ++j)
            #pragma unroll
            for (int r = 0; r < 4; ++r) d[i][j][r] = 0.f;

    issue(0);

    const int aRow = lane & 15;
    const int aK8  = (lane >> 4) * 8;
    const int bRow = (lane & 7) + ((lane >> 4) & 1) * 8;
    const int bK8  = ((lane >> 3) & 1) * 8;

    for (int t = 0; t < NT_; ++t) {
        if (t + 1 < NT_) { issue(t + 1); CP_WAIT(1); } else { CP_WAIT(0); }
        __syncthreads();

        const uint32_t st = sb + (t & 1) * STAGE_BYTES;
        #pragma unroll
        for (int ks = 0; ks < BK_; ks += 16) {
            uint32_t a[4][4];
            #pragma unroll
            for (int ms = 0; ms < 4; ++ms) {
                uint32_t addr = st + (uint32_t)(wm + ms*16 + aRow) * 80
                              + (uint32_t)(ks + aK8) * 2;
                LDSM_X4(a[ms][0], a[ms][1], a[ms][2], a[ms][3], addr);
            }
            uint32_t bh[4][2], bl[4][2];
            #pragma unroll
            for (int np = 0; np < 2; ++np) {
                uint32_t r0, r1, r2, r3;
                uint32_t boff = (uint32_t)(wn + np*16 + bRow) * 80
                              + (uint32_t)(ks + bK8) * 2;
                LDSM_X4(r0, r1, r2, r3, st + TILE_BYTES + boff);
                bh[np*2+0][0] = r0; bh[np*2+0][1] = r1;
                bh[np*2+1][0] = r2; bh[np*2+1][1] = r3;
                LDSM_X4(r0, r1, r2, r3, st + 2*TILE_BYTES + boff);
                bl[np*2+0][0] = r0; bl[np*2+0][1] = r1;
                bl[np*2+1][0] = r2; bl[np*2+1][1] = r3;
            }
            #pragma unroll
            for (int ms = 0; ms < 4; ++ms)
                #pragma unroll
                for (int ns = 0; ns < 4; ++ns)
                    MMA_F16(d[ms][ns], a[ms], bh[ns]);
            #pragma unroll
            for (int ms = 0; ms < 4; ++ms)
                #pragma unroll
                for (int ns = 0; ns < 4; ++ns)
                    MMA_F16(d[ms][ns], a[ms], bl[ns]);
        }
        __syncthreads();
    }

    const int g = lane >> 2, q = lane & 3;
    if (mode == 0) {
        __nv_bfloat16* Hi = (z == 0) ? g_qh : (z == 1) ? g_kh : g_vh;
        __nv_bfloat16* Lo = (z == 0) ? g_ql : (z == 1) ? g_kl : g_vl;
        #pragma unroll
        for (int ns = 0; ns < 4; ++ns) {
            const int col = n0 + wn + ns * 8 + q * 2;
            const float2 bv = *(const float2*)&bias[col];
            #pragma unroll
            for (int ms = 0; ms < 4; ++ms) {
                const int row = m0 + wm + ms * 16 + g;
                uint32_t h0, l0, h1, l1;
                split2(d[ms][ns][0] + bv.x, d[ms][ns][1] + bv.y, h0, l0);
                split2(d[ms][ns][2] + bv.x, d[ms][ns][3] + bv.y, h1, l1);
                *(uint32_t*)&Hi[(size_t)row * D_ + col]       = h0;
                *(uint32_t*)&Lo[(size_t)row * D_ + col]       = l0;
                *(uint32_t*)&Hi[(size_t)(row + 8) * D_ + col] = h1;
                *(uint32_t*)&Lo[(size_t)(row + 8) * D_ + col] = l1;
            }
        }
    } else {
        #pragma unroll
        for (int ns = 0; ns < 4; ++ns) {
            const int col = n0 + wn + ns * 8 + q * 2;
            const float2 bv = *(const float2*)&bias[col];
            #pragma unroll
            for (int ms = 0; ms < 4; ++ms) {
                const int row = m0 + wm + ms * 16 + g;
                float2 v0 = { d[ms][ns][0] + bv.x, d[ms][ns][1] + bv.y };
                float2 v1 = { d[ms][ns][2] + bv.x, d[ms][ns][3] + bv.y };
                *(float2*)&dout[(size_t)row * D_ + col]       = v0;
                *(float2*)&dout[(size_t)(row + 8) * D_ + col] = v1;
            }
        }
    }
}

// ---------------------------------------------------------------------------
// Tensor-core flash attention, 2 CTAs/SM:
//   smem = [Q region (4 tiles)] + [2-stage K/V ring (4 tiles each)]
//   Q fragments re-loaded from smem per tile (saves 32 regs); regs capped 128.
//   Pipeline: wait(0) -> sync -> issue(next) -> compute (1 barrier/iter, no WAR).
// ---------------------------------------------------------------------------
#define AROW_ 72
#define ATB_  (64 * AROW_ * 2)        // 9216
#define ASTG_ (4 * ATB_)              // 36864
#define ASMEM_ (3 * ASTG_)            // 110592 (Q + 2 stages)

__global__ void __launch_bounds__(256, 2) attn_kernel()
{
    const int qb = (int)(gridDim.x - 1 - blockIdx.x);   // heavy tiles first
    const int h  = blockIdx.y;
    const int b  = blockIdx.z;
    const int q0 = qb * 128;
    const size_t hoff = (size_t)h * HD_;

    const int tid  = threadIdx.x;
    const int lane = tid & 31;
    const int wid  = tid >> 5;
    const int g    = lane >> 2;
    const int qd   = lane & 3;

    const uint32_t sb = smem_u32(dsm);
    const uint32_t qreg = sb;                 // Q region
    const uint32_t ring = sb + ASTG_;         // 2-stage ring base

    const int c0 = tid * 2, c1 = tid * 2 + 1;
    const int r0c = c0 >> 3, q0c = c0 & 7;
    const int r1c = c1 >> 3, q1c = c1 & 7;

    // ---- Q into Q region (persistent): {Qhi r0-63, Qhi r64-127, Qlo r0-63, Qlo r64-127}
    {
        const size_t base0 = (size_t)(b*S_ + q0) * D_ + hoff;
        const size_t base1 = (size_t)(b*S_ + q0 + 64) * D_ + hoff;
        CP_ASYNC16(qreg + 0*ATB_ + r0c*144 + q0c*16, g_qh + base0 + r0c*D_ + q0c*8);
        CP_ASYNC16(qreg + 0*ATB_ + r1c*144 + q1c*16, g_qh + base0 + r1c*D_ + q1c*8);
        CP_ASYNC16(qreg + 1*ATB_ + r0c*144 + q0c*16, g_qh + base1 + r0c*D_ + q0c*8);
        CP_ASYNC16(qreg + 1*ATB_ + r1c*144 + q1c*16, g_qh + base1 + r1c*D_ + q1c*8);
        CP_ASYNC16(qreg + 2*ATB_ + r0c*144 + q0c*16, g_ql + base0 + r0c*D_ + q0c*8);
        CP_ASYNC16(qreg + 2*ATB_ + r1c*144 + q1c*16, g_ql + base0 + r1c*D_ + q1c*8);
        CP_ASYNC16(qreg + 3*ATB_ + r0c*144 + q0c*16, g_ql + base1 + r0c*D_ + q0c*8);
        CP_ASYNC16(qreg + 3*ATB_ + r1c*144 + q1c*16, g_ql + base1 + r1c*D_ + q1c*8);
        CP_COMMIT();
    }

    auto issue_tile = [&](int kt) {
        const uint32_t st = ring + (kt & 1) * ASTG_;
        const size_t base = (size_t)(b*S_ + kt*64) * D_ + hoff;
        const size_t o0 = base + r0c*D_ + q0c*8;
        const size_t o1 = base + r1c*D_ + q1c*8;
        const uint32_t d0 = r0c*144 + q0c*16;
        const uint32_t d1 = r1c*144 + q1c*16;
        CP_ASYNC16(st + 0*ATB_ + d0, g_kh + o0);
        CP_ASYNC16(st + 0*ATB_ + d1, g_kh + o1);
        CP_ASYNC16(st + 1*ATB_ + d0, g_kl + o0);
        CP_ASYNC16(st + 1*ATB_ + d1, g_kl + o1);
        CP_ASYNC16(st + 2*ATB_ + d0, g_vh + o0);
        CP_ASYNC16(st + 2*ATB_ + d1, g_vh + o1);
        CP_ASYNC16(st + 3*ATB_ + d0, g_vl + o0);
        CP_ASYNC16(st + 3*ATB_ + d1, g_vl + o1);
        CP_COMMIT();
    };

    issue_tile(0);

    float o[8][4];
    #pragma unroll
    for (int j = 0; j < 8; ++j)
        #pragma unroll
        for (int r = 0; r < 4; ++r) o[j][r] = 0.f;
    float mrow0 = -1e30f, mrow1 = -1e30f, lrow0 = 0.f, lrow1 = 0.f;

    const int wrow0 = q0 + wid * 16;

    // Q frag base addresses (per warp, fixed)
    const uint32_t qhbase = qreg + ((wid < 4) ? 0 : 1) * ATB_;
    const uint32_t qlbase = qreg + ((wid < 4) ? 2 : 3) * ATB_;
    const uint32_t qrr = (uint32_t)((wid & 3) * 16 + ((lane >> 3) & 1) * 8 + (lane & 7)) * 144
                       + (uint32_t)(((lane >> 4) & 1) * 8) * 2;

    const int kRow = ((lane >> 4) & 1) * 8 + (lane & 7);
    const int kK8  = ((lane >> 3) & 1) * 8;
    const int vRow = ((lane >> 3) & 1) * 8 + (lane & 7);
    const int vC8  = ((lane >> 4) & 1) * 8;

    const int nkt = 2 * (qb + 1);
    for (int kt = 0; kt < nkt; ++kt) {
        const int k0 = kt * 64;
        CP_WAIT(0);            // tile kt (and Q on first iter) resident
        __syncthreads();       // all warps done with the other ring buffer
        if (kt + 1 < nkt) issue_tile(kt + 1);

        const uint32_t st = ring + (kt & 1) * ASTG_;
        const uint32_t uKhi = st, uKlo = st + ATB_;
        const uint32_t uVhi = st + 2*ATB_, uVlo = st + 3*ATB_;

        if (k0 <= wrow0 + 15) {
            // ---- S: per kat, load Q frags from smem + batch K ldsm, wide sweeps
            float s[8][4];
            #pragma unroll
            for (int j = 0; j < 8; ++j)
                #pragma unroll
                for (int r = 0; r < 4; ++r) s[j][r] = 0.f;

            #pragma unroll
            for (int kat = 0; kat < 4; ++kat) {
                uint32_t qh4[4], ql4[4];
                const uint32_t qoff = qrr + (uint32_t)(kat * 16) * 2;
                LDSM_X4(qh4[0], qh4[1], qh4[2], qh4[3], qhbase + qoff);
                LDSM_X4(ql4[0], ql4[1], ql4[2], ql4[3], qlbase + qoff);

                uint32_t kh[4][4];
                #pragma unroll
                for (int jp = 0; jp < 4; ++jp) {
                    const uint32_t roff = (uint32_t)(jp*16 + kRow) * 144
                                        + (uint32_t)(kat*16 + kK8) * 2;
                    LDSM_X4(kh[jp][0], kh[jp][1], kh[jp][2], kh[jp][3], uKhi + roff);
                }
                #pragma unroll
                for (int jp = 0; jp < 4; ++jp) {
                    MMA_BF16(s[jp*2+0], qh4, (&kh[jp][0]));
                    MMA_BF16(s[jp*2+1], qh4, (&kh[jp][2]));
                }
                #pragma unroll
                for (int jp = 0; jp < 4; ++jp) {
                    MMA_BF16(s[jp*2+0], ql4, (&kh[jp][0]));
                    MMA_BF16(s[jp*2+1], ql4, (&kh[jp][2]));
                }
                uint32_t kl[4][4];
                #pragma unroll
                for (int jp = 0; jp < 4; ++jp) {
                    const uint32_t roff = (uint32_t)(jp*16 + kRow) * 144
                                        + (uint32_t)(kat*16 + kK8) * 2;
                    LDSM_X4(kl[jp][0], kl[jp][1], kl[jp][2], kl[jp][3], uKlo + roff);
                }
                #pragma unroll
                for (int jp = 0; jp < 4; ++jp) {
                    MMA_BF16(s[jp*2+0], qh4, (&kl[jp][0]));
                    MMA_BF16(s[jp*2+1], qh4, (&kl[jp][2]));
                }
            }

            // ---- online softmax
            const int row0 = wrow0 + g;
            const int row1 = row0 + 8;
            const bool needmask = (k0 + 63 > wrow0);
            float nm0 = mrow0, nm1 = mrow1;
            #pragma unroll
            for (int j = 0; j < 8; ++j) {
                const int col = k0 + j*8 + qd*2;
                float v0 = s[j][0] * 0.125f, v1 = s[j][1] * 0.125f;
                float v2 = s[j][2] * 0.125f, v3 = s[j][3] * 0.125f;
                if (needmask) {
                    if (col + 0 > row0) v0 = -1e30f;
                    if (col + 1 > row0) v1 = -1e30f;
                    if (col + 0 > row1) v2 = -1e30f;
                    if (col + 1 > row1) v3 = -1e30f;
                }
                s[j][0] = v0; s[j][1] = v1; s[j][2] = v2; s[j][3] = v3;
                nm0 = fmaxf(nm0, fmaxf(v0, v1));
                nm1 = fmaxf(nm1, fmaxf(v2, v3));
            }
            nm0 = fmaxf(nm0, __shfl_xor_sync(0xffffffffu, nm0, 1));
            nm0 = fmaxf(nm0, __shfl_xor_sync(0xffffffffu, nm0, 2));
            nm1 = fmaxf(nm1, __shfl_xor_sync(0xffffffffu, nm1, 1));
            nm1 = fmaxf(nm1, __shfl_xor_sync(0xffffffffu, nm1, 2));

            const float alpha0 = __expf(mrow0 - nm0);
            const float alpha1 = __expf(mrow1 - nm1);
            mrow0 = nm0; mrow1 = nm1;

            uint32_t phi[4][4], plo[4][4];
            float ps0 = 0.f, ps1 = 0.f;
            #pragma unroll
            for (int jp = 0; jp < 4; ++jp) {
                #pragma unroll
                for (int half = 0; half < 2; ++half) {
                    const int j = jp*2 + half;
                    const float p0 = __expf(s[j][0] - nm0);
                    const float p1 = __expf(s[j][1] - nm0);
                    const float p2 = __expf(s[j][2] - nm1);
                    const float p3 = __expf(s[j][3] - nm1);
                    ps0 += p0 + p1; ps1 += p2 + p3;
                    const uint32_t h01 = pack_bf16x2(p0, p1);
                    const uint32_t h23 = pack_bf16x2(p2, p3);
                    phi[jp][0 + half*2] = h01;
                    phi[jp][1 + half*2] = h23;
                    plo[jp][0 + half*2] = pack_bf16x2(p0 - lo_f(h01), p1 - hi_f(h01));
                    plo[jp][1 + half*2] = pack_bf16x2(p2 - lo_f(h23), p3 - hi_f(h23));
                }
            }
            ps0 += __shfl_xor_sync(0xffffffffu, ps0, 1);
            ps0 += __shfl_xor_sync(0xffffffffu, ps0, 2);
            ps1 += __shfl_xor_sync(0xffffffffu, ps1, 1);
            ps1 += __shfl_xor_sync(0xffffffffu, ps1, 2);
            lrow0 = lrow0 * alpha0 + ps0;
            lrow1 = lrow1 * alpha1 + ps1;
            #pragma unroll
            for (int j = 0; j < 8; ++j) {
                o[j][0] *= alpha0; o[j][1] *= alpha0;
                o[j][2] *= alpha1; o[j][3] *= alpha1;
            }

            // ---- PV: per kat, batch ldsm.T then wide sweeps
            #pragma unroll
            for (int kat = 0; kat < 4; ++kat) {
                uint32_t vh[4][4];
                #pragma unroll
                for (int jp = 0; jp < 4; ++jp) {
                    const uint32_t roff = (uint32_t)(kat*16 + vRow) * 144
                                        + (uint32_t)(jp*16 + vC8) * 2;
                    LDSM_X4T(vh[jp][0], vh[jp][1], vh[jp][2], vh[jp][3], uVhi + roff);
                }
                #pragma unroll
                for (int jp = 0; jp < 4; ++jp) {
                    MMA_BF16(o[jp*2+0], phi[kat], (&vh[jp][0]));
                    MMA_BF16(o[jp*2+1], phi[kat], (&vh[jp][2]));
                }
                #pragma unroll
                for (int jp = 0; jp < 4; ++jp) {
                    MMA_BF16(o[jp*2+0], plo[kat], (&vh[jp][0]));
                    MMA_BF16(o[jp*2+1], plo[kat], (&vh[jp][2]));
                }
                uint32_t vl[4][4];
                #pragma unroll
                for (int jp = 0; jp < 4; ++jp) {
                    const uint32_t roff = (uint32_t)(kat*16 + vRow) * 144
                                        + (uint32_t)(jp*16 + vC8) * 2;
                    LDSM_X4T(vl[jp][0], vl[jp][1], vl[jp][2], vl[jp][3], uVlo + roff);
                }
                #pragma unroll
                for (int jp = 0; jp < 4; ++jp) {
                    MMA_BF16(o[jp*2+0], phi[kat], (&vl[jp][0]));
                    MMA_BF16(o[jp*2+1], phi[kat], (&vl[jp][2]));
                }
            }
        }
    }

    // ---- normalize + write fp16 [B,S,D] directly
    const float inv0 = 1.f / lrow0;
    const float inv1 = 1.f / lrow1;
    const int row0 = q0 + wid*16 + g;
    #pragma unroll
    for (int j = 0; j < 8; ++j) {
        const int col = j*8 + qd*2;
        __half2 v0 = __floats2half2_rn(o[j][0] * inv0, o[j][1] * inv0);
        __half2 v1 = __floats2half2_rn(o[j][2] * inv1, o[j][3] * inv1);
        *(uint32_t*)&g_oh16[(size_t)(b*S_ + row0) * D_ + hoff + col]     = *(uint32_t*)&v0;
        *(uint32_t*)&g_oh16[(size_t)(b*S_ + row0 + 8) * D_ + hoff + col] = *(uint32_t*)&v1;
    }
}

// ---------------------------------------------------------------------------
extern "C" void kernel_launch(void* const* d_in, const int* in_sizes, int n_in,
                              void* d_out, int out_size)
{
    (void)in_sizes; (void)n_in; (void)out_size;
    const float* x  = (const float*)d_in[0];
    const float* Wq = (const float*)d_in[1];
    const float* bq = (const float*)d_in[2];
    const float* Wk = (const float*)d_in[3];
    const float* bk = (const float*)d_in[4];
    const float* Wv = (const float*)d_in[5];
    const float* bv = (const float*)d_in[6];
    const float* Wo = (const float*)d_in[7];
    const float* bo = (const float*)d_in[8];
    float* out = (float*)d_out;

    cudaFuncSetAttribute(mma_gemm, cudaFuncAttributeMaxDynamicSharedMemorySize, GSMEM_BYTES);
    cudaFuncSetAttribute(attn_kernel, cudaFuncAttributeMaxDynamicSharedMemorySize, ASMEM_);

    convert_h<<<(M_*D_/4 + 255)/256, 256>>>((const float4*)x);
    dim3 tg(D_/32, D_/32, 4);
    transpose_split<<<tg, dim3(32, 8)>>>(Wq, Wk, Wv, Wo);

    dim3 gq(D_/128, M_/128, 3);
    mma_gemm<<<gq, 256, GSMEM_BYTES>>>(0, bq, bk, bv, nullptr);

    dim3 ga(S_/128, H_, B_);
    attn_kernel<<<ga, 256, ASMEM_>>>();

    dim3 go(D_/128, M_/128, 1);
    mma_gemm<<<go, 256, GSMEM_BYTES>>>(1, bo, nullptr, nullptr, out);
}

// round 11
// speedup vs baseline: 1.4597x; 1.4597x over previous
#include <cuda_runtime.h>
#include <cuda_bf16.h>
#include <cuda_fp16.h>
#include <cstdint>

#define B_  2
#define S_  2048
#define D_  1024
#define H_  16
#define HD_ 64
#define M_  (B_*S_)   // 4096

// ---------------------------------------------------------------------------
// Scratch (allocation-free rule: static device globals)
// ---------------------------------------------------------------------------
__device__ __half g_xh16[M_*D_];              // fp16(x)
__device__ __half g_oh16[M_*D_];              // fp16(attention out)
__device__ __half g_wth[4][D_*D_];            // W^T fp16 [N,K]

// fp16 q (single) and split-fp16 k/v for tensor attention
__device__ __half g_q16[M_*D_];
__device__ __half g_kh16[M_*D_], g_kl16[M_*D_];
__device__ __half g_vh16[M_*D_], g_vl16[M_*D_];

// ---------------------------------------------------------------------------
__device__ __forceinline__ uint32_t smem_u32(const void* p) {
    uint32_t a;
    asm("{ .reg .u64 t; cvta.to.shared.u64 t, %1; cvt.u32.u64 %0, t; }" : "=r"(a) : "l"(p));
    return a;
}

#define CP_ASYNC16(dst, src) \
    asm volatile("cp.async.cg.shared.global [%0], [%1], 16;" :: "r"(dst), "l"(src))
#define CP_COMMIT()  asm volatile("cp.async.commit_group;" ::: "memory")
#define CP_WAIT(n)   asm volatile("cp.async.wait_group %0;" :: "n"(n) : "memory")

#define LDSM_X4(r0, r1, r2, r3, addr) \
    asm volatile("ldmatrix.sync.aligned.m8n8.x4.shared.b16 {%0,%1,%2,%3}, [%4];" \
        : "=r"(r0), "=r"(r1), "=r"(r2), "=r"(r3) : "r"(addr))

#define LDSM_X4T(r0, r1, r2, r3, addr) \
    asm volatile("ldmatrix.sync.aligned.m8n8.x4.trans.shared.b16 {%0,%1,%2,%3}, [%4];" \
        : "=r"(r0), "=r"(r1), "=r"(r2), "=r"(r3) : "r"(addr))

#define MMA_F16(d, a, b) \
    asm volatile("mma.sync.aligned.m16n8k16.row.col.f32.f16.f16.f32 " \
        "{%0,%1,%2,%3}, {%4,%5,%6,%7}, {%8,%9}, {%0,%1,%2,%3};" \
        : "+f"((d)[0]), "+f"((d)[1]), "+f"((d)[2]), "+f"((d)[3]) \
        : "r"((a)[0]), "r"((a)[1]), "r"((a)[2]), "r"((a)[3]), "r"((b)[0]), "r"((b)[1]))

// split two fp32 into (hi fp16x2, lo fp16x2)
__device__ __forceinline__ void split2h(float x, float y, uint32_t& hi, uint32_t& lo) {
    __half2 h = __floats2half2_rn(x, y);
    __half2 l = __floats2half2_rn(x - __half2float(h.x), y - __half2float(h.y));
    hi = *(uint32_t*)&h;
    lo = *(uint32_t*)&l;
}

// ---------------------------------------------------------------------------
// Convert fp32 x -> fp16 g_xh16.
// ---------------------------------------------------------------------------
__global__ void __launch_bounds__(256) convert_h(const float4* __restrict__ xin)
{
    const int i = blockIdx.x * 256 + threadIdx.x;
    const float4 v = xin[i];
    __half2 p0 = __floats2half2_rn(v.x, v.y);
    __half2 p1 = __floats2half2_rn(v.z, v.w);
    uint2 u; u.x = *(uint32_t*)&p0; u.y = *(uint32_t*)&p1;
    ((uint2*)g_xh16)[i] = u;
}

// ---------------------------------------------------------------------------
// Transpose: W[K,N] fp32 -> Wt[N,K] fp16. z selects Wq/Wk/Wv/Wo.
// ---------------------------------------------------------------------------
__global__ void __launch_bounds__(256) transpose_w(
    const float* __restrict__ Wq, const float* __restrict__ Wk,
    const float* __restrict__ Wv, const float* __restrict__ Wo)
{
    const float* W = (blockIdx.z == 0) ? Wq : (blockIdx.z == 1) ? Wk
                   : (blockIdx.z == 2) ? Wv : Wo;
    __half* Thi = g_wth[blockIdx.z];

    __shared__ float tile[32][33];
    const int tx = threadIdx.x, ty = threadIdx.y;
    const int k0 = blockIdx.x * 32, n0 = blockIdx.y * 32;

    #pragma unroll
    for (int j = 0; j < 32; j += 8)
        tile[ty + j][tx] = W[(size_t)(k0 + ty + j) * D_ + n0 + tx];
    __syncthreads();
    #pragma unroll
    for (int j = 0; j < 32; j += 8) {
        float v = tile[tx][ty + j];
        Thi[(size_t)(n0 + ty + j) * D_ + k0 + tx] = __float2half(v);
    }
}

// ---------------------------------------------------------------------------
// Single-pass fp16 GEMM: Out = A_fp16 * B_fp16^T + bias (fp32 accum).
// mode 0: QKV (z selects); epilogue writes fp16 q / split-fp16 k,v.
// mode 1: out projection -> dout fp32.
// ---------------------------------------------------------------------------
#define BK_   32
#define NT_   (D_ / BK_)
#define TILE_BYTES (128 * 40 * 2)        // 10240 (row stride 80B)
#define STAGE_BYTES (2 * TILE_BYTES)     // A, Bh
#define GSMEM_BYTES (2 * STAGE_BYTES)    // 40960

extern __shared__ char dsm[];

__global__ void __launch_bounds__(256, 2) mma_gemm(int mode,
    const float* __restrict__ b0, const float* __restrict__ b1,
    const float* __restrict__ b2, float* __restrict__ dout)
{
    const int z = mode ? 3 : blockIdx.z;
    const __half* A   = mode ? g_oh16 : g_xh16;
    const __half* Bh  = g_wth[z];
    const float* bias = mode ? b0 : (z == 0 ? b0 : (z == 1 ? b1 : b2));

    const int tid  = threadIdx.x;
    const int lane = tid & 31;
    const int wid  = tid >> 5;
    const int wm   = (wid & 1) * 64;
    const int wn   = (wid >> 1) * 32;
    const int m0 = blockIdx.y * 128;
    const int n0 = blockIdx.x * 128;

    const uint32_t sb = smem_u32(dsm);

    const int cA = tid * 2, cB = tid * 2 + 1;
    const int rA = cA >> 2, qA = cA & 3;
    const int rB = cB >> 2, qB = cB & 3;

    auto issue = [&](int t) {
        const int kc = t * BK_;
        const uint32_t st = sb + (t & 1) * STAGE_BYTES;
        CP_ASYNC16(st + rA * 80 + qA * 16, A  + (size_t)(m0 + rA) * D_ + kc + qA * 8);
        CP_ASYNC16(st + rB * 80 + qB * 16, A  + (size_t)(m0 + rB) * D_ + kc + qB * 8);
        CP_ASYNC16(st + TILE_BYTES + rA * 80 + qA * 16, Bh + (size_t)(n0 + rA) * D_ + kc + qA * 8);
        CP_ASYNC16(st + TILE_BYTES + rB * 80 + qB * 16, Bh + (size_t)(n0 + rB) * D_ + kc + qB * 8);
        CP_COMMIT();
    };

    float d[4][4][4];
    #pragma unroll
    for (int i = 0; i < 4; ++i)
        #pragma unroll
        for (int j = 0; j < 4; ++j)
            #pragma unroll
            for (int r = 0; r < 4; ++r) d[i][j][r] = 0.f;

    issue(0);

    const int aRow = lane & 15;
    const int aK8  = (lane >> 4) * 8;
    const int bRow = (lane & 7) + ((lane >> 4) & 1) * 8;
    const int bK8  = ((lane >> 3) & 1) * 8;

    for (int t = 0; t < NT_; ++t) {
        if (t + 1 < NT_) { issue(t + 1); CP_WAIT(1); } else { CP_WAIT(0); }
        __syncthreads();

        const uint32_t st = sb + (t & 1) * STAGE_BYTES;
        #pragma unroll
        for (int ks = 0; ks < BK_; ks += 16) {
            uint32_t a[4][4];
            #pragma unroll
            for (int ms = 0; ms < 4; ++ms) {
                uint32_t addr = st + (uint32_t)(wm + ms*16 + aRow) * 80
                              + (uint32_t)(ks + aK8) * 2;
                LDSM_X4(a[ms][0], a[ms][1], a[ms][2], a[ms][3], addr);
            }
            uint32_t bh[4][2];
            #pragma unroll
            for (int np = 0; np < 2; ++np) {
                uint32_t r0, r1, r2, r3;
                uint32_t boff = (uint32_t)(wn + np*16 + bRow) * 80
                              + (uint32_t)(ks + bK8) * 2;
                LDSM_X4(r0, r1, r2, r3, st + TILE_BYTES + boff);
                bh[np*2+0][0] = r0; bh[np*2+0][1] = r1;
                bh[np*2+1][0] = r2; bh[np*2+1][1] = r3;
            }
            #pragma unroll
            for (int ms = 0; ms < 4; ++ms)
                #pragma unroll
                for (int ns = 0; ns < 4; ++ns)
                    MMA_F16(d[ms][ns], a[ms], bh[ns]);
        }
        __syncthreads();
    }

    const int g = lane >> 2, q = lane & 3;
    if (mode == 0) {
        #pragma unroll
        for (int ns = 0; ns < 4; ++ns) {
            const int col = n0 + wn + ns * 8 + q * 2;
            const float2 bv = *(const float2*)&bias[col];
            #pragma unroll
            for (int ms = 0; ms < 4; ++ms) {
                const int row = m0 + wm + ms * 16 + g;
                const float x0 = d[ms][ns][0] + bv.x, y0 = d[ms][ns][1] + bv.y;
                const float x1 = d[ms][ns][2] + bv.x, y1 = d[ms][ns][3] + bv.y;
                if (z == 0) {
                    __half2 h0 = __floats2half2_rn(x0, y0);
                    __half2 h1 = __floats2half2_rn(x1, y1);
                    *(uint32_t*)&g_q16[(size_t)row * D_ + col]       = *(uint32_t*)&h0;
                    *(uint32_t*)&g_q16[(size_t)(row + 8) * D_ + col] = *(uint32_t*)&h1;
                } else {
                    __half* Hi = (z == 1) ? g_kh16 : g_vh16;
                    __half* Lo = (z == 1) ? g_kl16 : g_vl16;
                    uint32_t h0, l0, h1, l1;
                    split2h(x0, y0, h0, l0);
                    split2h(x1, y1, h1, l1);
                    *(uint32_t*)&Hi[(size_t)row * D_ + col]       = h0;
                    *(uint32_t*)&Lo[(size_t)row * D_ + col]       = l0;
                    *(uint32_t*)&Hi[(size_t)(row + 8) * D_ + col] = h1;
                    *(uint32_t*)&Lo[(size_t)(row + 8) * D_ + col] = l1;
                }
            }
        }
    } else {
        #pragma unroll
        for (int ns = 0; ns < 4; ++ns) {
            const int col = n0 + wn + ns * 8 + q * 2;
            const float2 bv = *(const float2*)&bias[col];
            #pragma unroll
            for (int ms = 0; ms < 4; ++ms) {
                const int row = m0 + wm + ms * 16 + g;
                float2 v0 = { d[ms][ns][0] + bv.x, d[ms][ns][1] + bv.y };
                float2 v1 = { d[ms][ns][2] + bv.x, d[ms][ns][3] + bv.y };
                *(float2*)&dout[(size_t)row * D_ + col]       = v0;
                *(float2*)&dout[(size_t)(row + 8) * D_ + col] = v1;
            }
        }
    }
}

// ---------------------------------------------------------------------------
// Tensor-core flash attention (fp16, 2-pass): Q,P fp16; K,V split fp16 hi/lo.
//   S = Q*Kh + Q*Kl ; O = P*Vh + P*Vl.  R8 pipeline shape (3-stage ring).
// ---------------------------------------------------------------------------
#define AROW_ 72
#define ATB_  (64 * AROW_ * 2)        // 9216
#define ASTG_ (4 * ATB_)              // {Kh, Kl, Vh, Vl}
#define ASMEM_ (3 * ASTG_)            // 110592

__global__ void __launch_bounds__(256, 1) attn_kernel()
{
    const int qb = (int)(gridDim.x - 1 - blockIdx.x);   // heavy tiles first
    const int h  = blockIdx.y;
    const int b  = blockIdx.z;
    const int q0 = qb * 128;
    const size_t hoff = (size_t)h * HD_;

    const int tid  = threadIdx.x;
    const int lane = tid & 31;
    const int wid  = tid >> 5;
    const int g    = lane >> 2;
    const int qd   = lane & 3;

    const uint32_t sb = smem_u32(dsm);

    const int c0 = tid * 2, c1 = tid * 2 + 1;
    const int r0c = c0 >> 3, q0c = c0 & 7;
    const int r1c = c1 >> 3, q1c = c1 & 7;

    // ---- Q (128x64 fp16) into stage-0 tiles 0,1 (temporary)
    {
        const size_t base0 = (size_t)(b*S_ + q0) * D_ + hoff;
        const size_t base1 = (size_t)(b*S_ + q0 + 64) * D_ + hoff;
        CP_ASYNC16(sb + 0*ATB_ + r0c*144 + q0c*16, g_q16 + base0 + r0c*D_ + q0c*8);
        CP_ASYNC16(sb + 0*ATB_ + r1c*144 + q1c*16, g_q16 + base0 + r1c*D_ + q1c*8);
        CP_ASYNC16(sb + 1*ATB_ + r0c*144 + q0c*16, g_q16 + base1 + r0c*D_ + q0c*8);
        CP_ASYNC16(sb + 1*ATB_ + r1c*144 + q1c*16, g_q16 + base1 + r1c*D_ + q1c*8);
        CP_COMMIT();
    }

    auto issue_tile = [&](int kt) {
        const int stg = (kt + 1) % 3;
        const uint32_t st = sb + stg * ASTG_;
        const size_t base = (size_t)(b*S_ + kt*64) * D_ + hoff;
        const size_t o0 = base + r0c*D_ + q0c*8;
        const size_t o1 = base + r1c*D_ + q1c*8;
        const uint32_t d0 = r0c*144 + q0c*16;
        const uint32_t d1 = r1c*144 + q1c*16;
        CP_ASYNC16(st + 0*ATB_ + d0, g_kh16 + o0);
        CP_ASYNC16(st + 0*ATB_ + d1, g_kh16 + o1);
        CP_ASYNC16(st + 1*ATB_ + d0, g_kl16 + o0);
        CP_ASYNC16(st + 1*ATB_ + d1, g_kl16 + o1);
        CP_ASYNC16(st + 2*ATB_ + d0, g_vh16 + o0);
        CP_ASYNC16(st + 2*ATB_ + d1, g_vh16 + o1);
        CP_ASYNC16(st + 3*ATB_ + d0, g_vl16 + o0);
        CP_ASYNC16(st + 3*ATB_ + d1, g_vl16 + o1);
        CP_COMMIT();
    };

    issue_tile(0);          // -> stage 1
    CP_WAIT(1);             // Q group done
    __syncthreads();

    // ---- Q fragments (fp16, 16 regs)
    uint32_t qf[4][4];
    {
        const uint32_t qbase = sb + ((wid < 4) ? 0 : 1) * ATB_;
        const int rr = (wid & 3) * 16 + ((lane >> 3) & 1) * 8 + (lane & 7);
        #pragma unroll
        for (int kat = 0; kat < 4; ++kat) {
            const uint32_t koff = (uint32_t)(kat * 16 + ((lane >> 4) & 1) * 8) * 2;
            LDSM_X4(qf[kat][0], qf[kat][1], qf[kat][2], qf[kat][3],
                    qbase + (uint32_t)rr * 144 + koff);
        }
    }

    float o[8][4];
    #pragma unroll
    for (int j = 0; j < 8; ++j)
        #pragma unroll
        for (int r = 0; r < 4; ++r) o[j][r] = 0.f;
    float mrow0 = -1e30f, mrow1 = -1e30f, lrow0 = 0.f, lrow1 = 0.f;

    const int wrow0 = q0 + wid * 16;

    const int kRow = ((lane >> 4) & 1) * 8 + (lane & 7);
    const int kK8  = ((lane >> 3) & 1) * 8;
    const int vRow = ((lane >> 3) & 1) * 8 + (lane & 7);
    const int vC8  = ((lane >> 4) & 1) * 8;

    const int nkt = 2 * (qb + 1);
    for (int kt = 0; kt < nkt; ++kt) {
        const int k0 = kt * 64;
        if (kt + 1 < nkt) { issue_tile(kt + 1); CP_WAIT(1); } else { CP_WAIT(0); }
        __syncthreads();

        const uint32_t st = sb + ((kt + 1) % 3) * ASTG_;
        const uint32_t uKhi = st, uKlo = st + ATB_;
        const uint32_t uVhi = st + 2*ATB_, uVlo = st + 3*ATB_;

        if (k0 <= wrow0 + 15) {
            // ---- S = Q*Kh + Q*Kl
            float s[8][4];
            #pragma unroll
            for (int j = 0; j < 8; ++j)
                #pragma unroll
                for (int r = 0; r < 4; ++r) s[j][r] = 0.f;

            #pragma unroll
            for (int kat = 0; kat < 4; ++kat) {
                uint32_t kh[4][4];
                #pragma unroll
                for (int jp = 0; jp < 4; ++jp) {
                    const uint32_t roff = (uint32_t)(jp*16 + kRow) * 144
                                        + (uint32_t)(kat*16 + kK8) * 2;
                    LDSM_X4(kh[jp][0], kh[jp][1], kh[jp][2], kh[jp][3], uKhi + roff);
                }
                #pragma unroll
                for (int jp = 0; jp < 4; ++jp) {
                    MMA_F16(s[jp*2+0], qf[kat], (&kh[jp][0]));
                    MMA_F16(s[jp*2+1], qf[kat], (&kh[jp][2]));
                }
                uint32_t kl[4][4];
                #pragma unroll
                for (int jp = 0; jp < 4; ++jp) {
                    const uint32_t roff = (uint32_t)(jp*16 + kRow) * 144
                                        + (uint32_t)(kat*16 + kK8) * 2;
                    LDSM_X4(kl[jp][0], kl[jp][1], kl[jp][2], kl[jp][3], uKlo + roff);
                }
                #pragma unroll
                for (int jp = 0; jp < 4; ++jp) {
                    MMA_F16(s[jp*2+0], qf[kat], (&kl[jp][0]));
                    MMA_F16(s[jp*2+1], qf[kat], (&kl[jp][2]));
                }
            }

            // ---- online softmax
            const int row0 = wrow0 + g;
            const int row1 = row0 + 8;
            const bool needmask = (k0 + 63 > wrow0);
            float nm0 = mrow0, nm1 = mrow1;
            #pragma unroll
            for (int j = 0; j < 8; ++j) {
                const int col = k0 + j*8 + qd*2;
                float v0 = s[j][0] * 0.125f, v1 = s[j][1] * 0.125f;
                float v2 = s[j][2] * 0.125f, v3 = s[j][3] * 0.125f;
                if (needmask) {
                    if (col + 0 > row0) v0 = -1e30f;
                    if (col + 1 > row0) v1 = -1e30f;
                    if (col + 0 > row1) v2 = -1e30f;
                    if (col + 1 > row1) v3 = -1e30f;
                }
                s[j][0] = v0; s[j][1] = v1; s[j][2] = v2; s[j][3] = v3;
                nm0 = fmaxf(nm0, fmaxf(v0, v1));
                nm1 = fmaxf(nm1, fmaxf(v2, v3));
            }
            nm0 = fmaxf(nm0, __shfl_xor_sync(0xffffffffu, nm0, 1));
            nm0 = fmaxf(nm0, __shfl_xor_sync(0xffffffffu, nm0, 2));
            nm1 = fmaxf(nm1, __shfl_xor_sync(0xffffffffu, nm1, 1));
            nm1 = fmaxf(nm1, __shfl_xor_sync(0xffffffffu, nm1, 2));

            const float alpha0 = __expf(mrow0 - nm0);
            const float alpha1 = __expf(mrow1 - nm1);
            mrow0 = nm0; mrow1 = nm1;

            uint32_t pf[4][4];
            float ps0 = 0.f, ps1 = 0.f;
            #pragma unroll
            for (int jp = 0; jp < 4; ++jp) {
                #pragma unroll
                for (int half = 0; half < 2; ++half) {
                    const int j = jp*2 + half;
                    const float p0 = __expf(s[j][0] - nm0);
                    const float p1 = __expf(s[j][1] - nm0);
                    const float p2 = __expf(s[j][2] - nm1);
                    const float p3 = __expf(s[j][3] - nm1);
                    ps0 += p0 + p1; ps1 += p2 + p3;
                    __half2 h01 = __floats2half2_rn(p0, p1);
                    __half2 h23 = __floats2half2_rn(p2, p3);
                    pf[jp][0 + half*2] = *(uint32_t*)&h01;
                    pf[jp][1 + half*2] = *(uint32_t*)&h23;
                }
            }
            ps0 += __shfl_xor_sync(0xffffffffu, ps0, 1);
            ps0 += __shfl_xor_sync(0xffffffffu, ps0, 2);
            ps1 += __shfl_xor_sync(0xffffffffu, ps1, 1);
            ps1 += __shfl_xor_sync(0xffffffffu, ps1, 2);
            lrow0 = lrow0 * alpha0 + ps0;
            lrow1 = lrow1 * alpha1 + ps1;
            #pragma unroll
            for (int j = 0; j < 8; ++j) {
                o[j][0] *= alpha0; o[j][1] *= alpha0;
                o[j][2] *= alpha1; o[j][3] *= alpha1;
            }

            // ---- O += P*Vh + P*Vl
            #pragma unroll
            for (int kat = 0; kat < 4; ++kat) {
                uint32_t vh[4][4];
                #pragma unroll
                for (int jp = 0; jp < 4; ++jp) {
                    const uint32_t roff = (uint32_t)(kat*16 + vRow) * 144
                                        + (uint32_t)(jp*16 + vC8) * 2;
                    LDSM_X4T(vh[jp][0], vh[jp][1], vh[jp][2], vh[jp][3], uVhi + roff);
                }
                #pragma unroll
                for (int jp = 0; jp < 4; ++jp) {
                    MMA_F16(o[jp*2+0], pf[kat], (&vh[jp][0]));
                    MMA_F16(o[jp*2+1], pf[kat], (&vh[jp][2]));
                }
                uint32_t vl[4][4];
                #pragma unroll
                for (int jp = 0; jp < 4; ++jp) {
                    const uint32_t roff = (uint32_t)(kat*16 + vRow) * 144
                                        + (uint32_t)(jp*16 + vC8) * 2;
                    LDSM_X4T(vl[jp][0], vl[jp][1], vl[jp][2], vl[jp][3], uVlo + roff);
                }
                #pragma unroll
                for (int jp = 0; jp < 4; ++jp) {
                    MMA_F16(o[jp*2+0], pf[kat], (&vl[jp][0]));
                    MMA_F16(o[jp*2+1], pf[kat], (&vl[jp][2]));
                }
            }
        }
    }

    // ---- normalize + write fp16 [B,S,D]
    const float inv0 = 1.f / lrow0;
    const float inv1 = 1.f / lrow1;
    const int row0 = q0 + wid*16 + g;
    #pragma unroll
    for (int j = 0; j < 8; ++j) {
        const int col = j*8 + qd*2;
        __half2 v0 = __floats2half2_rn(o[j][0] * inv0, o[j][1] * inv0);
        __half2 v1 = __floats2half2_rn(o[j][2] * inv1, o[j][3] * inv1);
        *(uint32_t*)&g_oh16[(size_t)(b*S_ + row0) * D_ + hoff + col]     = *(uint32_t*)&v0;
        *(uint32_t*)&g_oh16[(size_t)(b*S_ + row0 + 8) * D_ + hoff + col] = *(uint32_t*)&v1;
    }
}

// ---------------------------------------------------------------------------
extern "C" void kernel_launch(void* const* d_in, const int* in_sizes, int n_in,
                              void* d_out, int out_size)
{
    (void)in_sizes; (void)n_in; (void)out_size;
    const float* x  = (const float*)d_in[0];
    const float* Wq = (const float*)d_in[1];
    const float* bq = (const float*)d_in[2];
    const float* Wk = (const float*)d_in[3];
    const float* bk = (const float*)d_in[4];
    const float* Wv = (const float*)d_in[5];
    const float* bv = (const float*)d_in[6];
    const float* Wo = (const float*)d_in[7];
    const float* bo = (const float*)d_in[8];
    float* out = (float*)d_out;

    cudaFuncSetAttribute(mma_gemm, cudaFuncAttributeMaxDynamicSharedMemorySize, GSMEM_BYTES);
    cudaFuncSetAttribute(attn_kernel, cudaFuncAttributeMaxDynamicSharedMemorySize, ASMEM_);

    convert_h<<<(M_*D_/4 + 255)/256, 256>>>((const float4*)x);
    dim3 tg(D_/32, D_/32, 4);
    transpose_w<<<tg, dim3(32, 8)>>>(Wq, Wk, Wv, Wo);

    dim3 gq(D_/128, M_/128, 3);
    mma_gemm<<<gq, 256, GSMEM_BYTES>>>(0, bq, bk, bv, nullptr);

    dim3 ga(S_/128, H_, B_);
    attn_kernel<<<ga, 256, ASMEM_>>>();

    dim3 go(D_/128, M_/128, 1);
    mma_gemm<<<go, 256, GSMEM_BYTES>>>(1, bo, nullptr, nullptr, out);
}

// round 12
// speedup vs baseline: 1.4868x; 1.0185x over previous
#include <cuda_runtime.h>
#include <cuda_bf16.h>
#include <cuda_fp16.h>
#include <cstdint>

#define B_  2
#define S_  2048
#define D_  1024
#define H_  16
#define HD_ 64
#define M_  (B_*S_)   // 4096

// ---------------------------------------------------------------------------
// Scratch (allocation-free rule: static device globals)
// ---------------------------------------------------------------------------
__device__ __half g_xh16[M_*D_];              // fp16(x)
__device__ __half g_oh16[M_*D_];              // fp16(attention out)
__device__ __half g_wth[4][D_*D_];            // W^T fp16 [N,K]

// fp16 q/v (single) and split-fp16 k for tensor attention
__device__ __half g_q16[M_*D_];
__device__ __half g_kh16[M_*D_], g_kl16[M_*D_];
__device__ __half g_v16[M_*D_];

// ---------------------------------------------------------------------------
__device__ __forceinline__ uint32_t smem_u32(const void* p) {
    uint32_t a;
    asm("{ .reg .u64 t; cvta.to.shared.u64 t, %1; cvt.u32.u64 %0, t; }" : "=r"(a) : "l"(p));
    return a;
}

#define CP_ASYNC16(dst, src) \
    asm volatile("cp.async.cg.shared.global [%0], [%1], 16;" :: "r"(dst), "l"(src))
#define CP_COMMIT()  asm volatile("cp.async.commit_group;" ::: "memory")
#define CP_WAIT(n)   asm volatile("cp.async.wait_group %0;" :: "n"(n) : "memory")

#define LDSM_X4(r0, r1, r2, r3, addr) \
    asm volatile("ldmatrix.sync.aligned.m8n8.x4.shared.b16 {%0,%1,%2,%3}, [%4];" \
        : "=r"(r0), "=r"(r1), "=r"(r2), "=r"(r3) : "r"(addr))

#define LDSM_X4T(r0, r1, r2, r3, addr) \
    asm volatile("ldmatrix.sync.aligned.m8n8.x4.trans.shared.b16 {%0,%1,%2,%3}, [%4];" \
        : "=r"(r0), "=r"(r1), "=r"(r2), "=r"(r3) : "r"(addr))

#define MMA_F16(d, a, b) \
    asm volatile("mma.sync.aligned.m16n8k16.row.col.f32.f16.f16.f32 " \
        "{%0,%1,%2,%3}, {%4,%5,%6,%7}, {%8,%9}, {%0,%1,%2,%3};" \
        : "+f"((d)[0]), "+f"((d)[1]), "+f"((d)[2]), "+f"((d)[3]) \
        : "r"((a)[0]), "r"((a)[1]), "r"((a)[2]), "r"((a)[3]), "r"((b)[0]), "r"((b)[1]))

// split two fp32 into (hi fp16x2, lo fp16x2)
__device__ __forceinline__ void split2h(float x, float y, uint32_t& hi, uint32_t& lo) {
    __half2 h = __floats2half2_rn(x, y);
    __half2 l = __floats2half2_rn(x - __half2float(h.x), y - __half2float(h.y));
    hi = *(uint32_t*)&h;
    lo = *(uint32_t*)&l;
}

// ---------------------------------------------------------------------------
// Convert fp32 x -> fp16 g_xh16.
// ---------------------------------------------------------------------------
__global__ void __launch_bounds__(256) convert_h(const float4* __restrict__ xin)
{
    const int i = blockIdx.x * 256 + threadIdx.x;
    const float4 v = xin[i];
    __half2 p0 = __floats2half2_rn(v.x, v.y);
    __half2 p1 = __floats2half2_rn(v.z, v.w);
    uint2 u; u.x = *(uint32_t*)&p0; u.y = *(uint32_t*)&p1;
    ((uint2*)g_xh16)[i] = u;
}

// ---------------------------------------------------------------------------
// Transpose: W[K,N] fp32 -> Wt[N,K] fp16. z selects Wq/Wk/Wv/Wo.
// ---------------------------------------------------------------------------
__global__ void __launch_bounds__(256) transpose_w(
    const float* __restrict__ Wq, const float* __restrict__ Wk,
    const float* __restrict__ Wv, const float* __restrict__ Wo)
{
    const float* W = (blockIdx.z == 0) ? Wq : (blockIdx.z == 1) ? Wk
                   : (blockIdx.z == 2) ? Wv : Wo;
    __half* Thi = g_wth[blockIdx.z];

    __shared__ float tile[32][33];
    const int tx = threadIdx.x, ty = threadIdx.y;
    const int k0 = blockIdx.x * 32, n0 = blockIdx.y * 32;

    #pragma unroll
    for (int j = 0; j < 32; j += 8)
        tile[ty + j][tx] = W[(size_t)(k0 + ty + j) * D_ + n0 + tx];
    __syncthreads();
    #pragma unroll
    for (int j = 0; j < 32; j += 8) {
        float v = tile[tx][ty + j];
        Thi[(size_t)(n0 + ty + j) * D_ + k0 + tx] = __float2half(v);
    }
}

// ---------------------------------------------------------------------------
// Single-pass fp16 GEMM, BK=64: Out = A_fp16 * B_fp16^T + bias (fp32 accum).
// Tile rows padded to 144B (64 halves + 8 pad) for conflict-free ldmatrix.
// mode 0: QKV (z selects); epilogue writes fp16 q/v, split-fp16 k.
// mode 1: out projection -> dout fp32.
// ---------------------------------------------------------------------------
#define GBK_  64
#define GNT_  (D_ / GBK_)                 // 16
#define GROWB_ 144                        // bytes per row
#define GTILE_ (128 * GROWB_)             // 18432
#define GSTAGE_ (2 * GTILE_)              // A, B
#define GSMEM_BYTES (2 * GSTAGE_)         // 73728

extern __shared__ char dsm[];

__global__ void __launch_bounds__(256, 2) mma_gemm(int mode,
    const float* __restrict__ b0, const float* __restrict__ b1,
    const float* __restrict__ b2, float* __restrict__ dout)
{
    const int z = mode ? 3 : blockIdx.z;
    const __half* A   = mode ? g_oh16 : g_xh16;
    const __half* Bh  = g_wth[z];
    const float* bias = mode ? b0 : (z == 0 ? b0 : (z == 1 ? b1 : b2));

    const int tid  = threadIdx.x;
    const int lane = tid & 31;
    const int wid  = tid >> 5;
    const int wm   = (wid & 1) * 64;
    const int wn   = (wid >> 1) * 32;
    const int m0 = blockIdx.y * 128;
    const int n0 = blockIdx.x * 128;

    const uint32_t sb = smem_u32(dsm);

    // staging: per tile, each thread does 4 x 16B within one row half
    const int sr = tid >> 1;               // row 0..127
    const int sq = (tid & 1) * 4;          // 16B-chunk base 0 or 4

    auto issue = [&](int t) {
        const int kc = t * GBK_;
        const uint32_t st = sb + (t & 1) * GSTAGE_;
        const __half* Ap = A  + (size_t)(m0 + sr) * D_ + kc + sq * 8;
        const __half* Bp = Bh + (size_t)(n0 + sr) * D_ + kc + sq * 8;
        const uint32_t d0 = (uint32_t)sr * GROWB_ + sq * 16;
        #pragma unroll
        for (int u = 0; u < 4; ++u) {
            CP_ASYNC16(st + d0 + u * 16,          Ap + u * 8);
            CP_ASYNC16(st + GTILE_ + d0 + u * 16, Bp + u * 8);
        }
        CP_COMMIT();
    };

    float d[4][4][4];
    #pragma unroll
    for (int i = 0; i < 4; ++i)
        #pragma unroll
        for (int j = 0; j < 4; ++j)
            #pragma unroll
            for (int r = 0; r < 4; ++r) d[i][j][r] = 0.f;

    issue(0);

    const int aRow = lane & 15;
    const int aK8  = (lane >> 4) * 8;
    const int bRow = (lane & 7) + ((lane >> 4) & 1) * 8;
    const int bK8  = ((lane >> 3) & 1) * 8;

    for (int t = 0; t < GNT_; ++t) {
        if (t + 1 < GNT_) { issue(t + 1); CP_WAIT(1); } else { CP_WAIT(0); }
        __syncthreads();

        const uint32_t st = sb + (t & 1) * GSTAGE_;
        #pragma unroll
        for (int ks = 0; ks < GBK_; ks += 16) {
            uint32_t a[4][4];
            #pragma unroll
            for (int ms = 0; ms < 4; ++ms) {
                uint32_t addr = st + (uint32_t)(wm + ms*16 + aRow) * GROWB_
                              + (uint32_t)(ks + aK8) * 2;
                LDSM_X4(a[ms][0], a[ms][1], a[ms][2], a[ms][3], addr);
            }
            uint32_t bh[4][2];
            #pragma unroll
            for (int np = 0; np < 2; ++np) {
                uint32_t r0, r1, r2, r3;
                uint32_t boff = (uint32_t)(wn + np*16 + bRow) * GROWB_
                              + (uint32_t)(ks + bK8) * 2;
                LDSM_X4(r0, r1, r2, r3, st + GTILE_ + boff);
                bh[np*2+0][0] = r0; bh[np*2+0][1] = r1;
                bh[np*2+1][0] = r2; bh[np*2+1][1] = r3;
            }
            #pragma unroll
            for (int ms = 0; ms < 4; ++ms)
                #pragma unroll
                for (int ns = 0; ns < 4; ++ns)
                    MMA_F16(d[ms][ns], a[ms], bh[ns]);
        }
        __syncthreads();
    }

    const int g = lane >> 2, q = lane & 3;
    if (mode == 0) {
        #pragma unroll
        for (int ns = 0; ns < 4; ++ns) {
            const int col = n0 + wn + ns * 8 + q * 2;
            const float2 bv = *(const float2*)&bias[col];
            #pragma unroll
            for (int ms = 0; ms < 4; ++ms) {
                const int row = m0 + wm + ms * 16 + g;
                const float x0 = d[ms][ns][0] + bv.x, y0 = d[ms][ns][1] + bv.y;
                const float x1 = d[ms][ns][2] + bv.x, y1 = d[ms][ns][3] + bv.y;
                if (z == 1) {   // K: split fp16
                    uint32_t h0, l0, h1, l1;
                    split2h(x0, y0, h0, l0);
                    split2h(x1, y1, h1, l1);
                    *(uint32_t*)&g_kh16[(size_t)row * D_ + col]       = h0;
                    *(uint32_t*)&g_kl16[(size_t)row * D_ + col]       = l0;
                    *(uint32_t*)&g_kh16[(size_t)(row + 8) * D_ + col] = h1;
                    *(uint32_t*)&g_kl16[(size_t)(row + 8) * D_ + col] = l1;
                } else {        // Q or V: single fp16
                    __half* Dst = (z == 0) ? g_q16 : g_v16;
                    __half2 h0 = __floats2half2_rn(x0, y0);
                    __half2 h1 = __floats2half2_rn(x1, y1);
                    *(uint32_t*)&Dst[(size_t)row * D_ + col]       = *(uint32_t*)&h0;
                    *(uint32_t*)&Dst[(size_t)(row + 8) * D_ + col] = *(uint32_t*)&h1;
                }
            }
        }
    } else {
        #pragma unroll
        for (int ns = 0; ns < 4; ++ns) {
            const int col = n0 + wn + ns * 8 + q * 2;
            const float2 bv = *(const float2*)&bias[col];
            #pragma unroll
            for (int ms = 0; ms < 4; ++ms) {
                const int row = m0 + wm + ms * 16 + g;
                float2 v0 = { d[ms][ns][0] + bv.x, d[ms][ns][1] + bv.y };
                float2 v1 = { d[ms][ns][2] + bv.x, d[ms][ns][3] + bv.y };
                *(float2*)&dout[(size_t)row * D_ + col]       = v0;
                *(float2*)&dout[(size_t)(row + 8) * D_ + col] = v1;
            }
        }
    }
}

// ---------------------------------------------------------------------------
// Tensor-core flash attention: Q,P,V fp16 single; K split fp16 hi/lo.
//   S = Q*Kh + Q*Kl ; O = P*V.  3-stage ring of {Kh, Kl, V}.
// ---------------------------------------------------------------------------
#define AROW_ 72
#define ATB_  (64 * AROW_ * 2)        // 9216
#define ASTG_ (3 * ATB_)              // {Kh, Kl, V} = 27648
#define ASMEM_ (3 * ASTG_)            // 82944

__global__ void __launch_bounds__(256, 1) attn_kernel()
{
    const int qb = (int)(gridDim.x - 1 - blockIdx.x);   // heavy tiles first
    const int h  = blockIdx.y;
    const int b  = blockIdx.z;
    const int q0 = qb * 128;
    const size_t hoff = (size_t)h * HD_;

    const int tid  = threadIdx.x;
    const int lane = tid & 31;
    const int wid  = tid >> 5;
    const int g    = lane >> 2;
    const int qd   = lane & 3;

    const uint32_t sb = smem_u32(dsm);

    const int c0 = tid * 2, c1 = tid * 2 + 1;
    const int r0c = c0 >> 3, q0c = c0 & 7;
    const int r1c = c1 >> 3, q1c = c1 & 7;

    // ---- Q (128x64 fp16) into stage-0 tiles 0,1 (temporary)
    {
        const size_t base0 = (size_t)(b*S_ + q0) * D_ + hoff;
        const size_t base1 = (size_t)(b*S_ + q0 + 64) * D_ + hoff;
        CP_ASYNC16(sb + 0*ATB_ + r0c*144 + q0c*16, g_q16 + base0 + r0c*D_ + q0c*8);
        CP_ASYNC16(sb + 0*ATB_ + r1c*144 + q1c*16, g_q16 + base0 + r1c*D_ + q1c*8);
        CP_ASYNC16(sb + 1*ATB_ + r0c*144 + q0c*16, g_q16 + base1 + r0c*D_ + q0c*8);
        CP_ASYNC16(sb + 1*ATB_ + r1c*144 + q1c*16, g_q16 + base1 + r1c*D_ + q1c*8);
        CP_COMMIT();
    }

    auto issue_tile = [&](int kt) {
        const int stg = (kt + 1) % 3;
        const uint32_t st = sb + stg * ASTG_;
        const size_t base = (size_t)(b*S_ + kt*64) * D_ + hoff;
        const size_t o0 = base + r0c*D_ + q0c*8;
        const size_t o1 = base + r1c*D_ + q1c*8;
        const uint32_t d0 = r0c*144 + q0c*16;
        const uint32_t d1 = r1c*144 + q1c*16;
        CP_ASYNC16(st + 0*ATB_ + d0, g_kh16 + o0);
        CP_ASYNC16(st + 0*ATB_ + d1, g_kh16 + o1);
        CP_ASYNC16(st + 1*ATB_ + d0, g_kl16 + o0);
        CP_ASYNC16(st + 1*ATB_ + d1, g_kl16 + o1);
        CP_ASYNC16(st + 2*ATB_ + d0, g_v16 + o0);
        CP_ASYNC16(st + 2*ATB_ + d1, g_v16 + o1);
        CP_COMMIT();
    };

    issue_tile(0);          // -> stage 1
    CP_WAIT(1);             // Q group done
    __syncthreads();

    // ---- Q fragments (fp16, 16 regs)
    uint32_t qf[4][4];
    {
        const uint32_t qbase = sb + ((wid < 4) ? 0 : 1) * ATB_;
        const int rr = (wid & 3) * 16 + ((lane >> 3) & 1) * 8 + (lane & 7);
        #pragma unroll
        for (int kat = 0; kat < 4; ++kat) {
            const uint32_t koff = (uint32_t)(kat * 16 + ((lane >> 4) & 1) * 8) * 2;
            LDSM_X4(qf[kat][0], qf[kat][1], qf[kat][2], qf[kat][3],
                    qbase + (uint32_t)rr * 144 + koff);
        }
    }

    float o[8][4];
    #pragma unroll
    for (int j = 0; j < 8; ++j)
        #pragma unroll
        for (int r = 0; r < 4; ++r) o[j][r] = 0.f;
    float mrow0 = -1e30f, mrow1 = -1e30f, lrow0 = 0.f, lrow1 = 0.f;

    const int wrow0 = q0 + wid * 16;

    const int kRow = ((lane >> 4) & 1) * 8 + (lane & 7);
    const int kK8  = ((lane >> 3) & 1) * 8;
    const int vRow = ((lane >> 3) & 1) * 8 + (lane & 7);
    const int vC8  = ((lane >> 4) & 1) * 8;

    const int nkt = 2 * (qb + 1);
    for (int kt = 0; kt < nkt; ++kt) {
        const int k0 = kt * 64;
        if (kt + 1 < nkt) { issue_tile(kt + 1); CP_WAIT(1); } else { CP_WAIT(0); }
        __syncthreads();

        const uint32_t st = sb + ((kt + 1) % 3) * ASTG_;
        const uint32_t uKhi = st, uKlo = st + ATB_;
        const uint32_t uV = st + 2*ATB_;

        if (k0 <= wrow0 + 15) {
            // ---- S = Q*Kh + Q*Kl
            float s[8][4];
            #pragma unroll
            for (int j = 0; j < 8; ++j)
                #pragma unroll
                for (int r = 0; r < 4; ++r) s[j][r] = 0.f;

            #pragma unroll
            for (int kat = 0; kat < 4; ++kat) {
                uint32_t kh[4][4];
                #pragma unroll
                for (int jp = 0; jp < 4; ++jp) {
                    const uint32_t roff = (uint32_t)(jp*16 + kRow) * 144
                                        + (uint32_t)(kat*16 + kK8) * 2;
                    LDSM_X4(kh[jp][0], kh[jp][1], kh[jp][2], kh[jp][3], uKhi + roff);
                }
                #pragma unroll
                for (int jp = 0; jp < 4; ++jp) {
                    MMA_F16(s[jp*2+0], qf[kat], (&kh[jp][0]));
                    MMA_F16(s[jp*2+1], qf[kat], (&kh[jp][2]));
                }
                uint32_t kl[4][4];
                #pragma unroll
                for (int jp = 0; jp < 4; ++jp) {
                    const uint32_t roff = (uint32_t)(jp*16 + kRow) * 144
                                        + (uint32_t)(kat*16 + kK8) * 2;
                    LDSM_X4(kl[jp][0], kl[jp][1], kl[jp][2], kl[jp][3], uKlo + roff);
                }
                #pragma unroll
                for (int jp = 0; jp < 4; ++jp) {
                    MMA_F16(s[jp*2+0], qf[kat], (&kl[jp][0]));
                    MMA_F16(s[jp*2+1], qf[kat], (&kl[jp][2]));
                }
            }

            // ---- online softmax
            const int row0 = wrow0 + g;
            const int row1 = row0 + 8;
            const bool needmask = (k0 + 63 > wrow0);
            float nm0 = mrow0, nm1 = mrow1;
            #pragma unroll
            for (int j = 0; j < 8; ++j) {
                const int col = k0 + j*8 + qd*2;
                float v0 = s[j][0] * 0.125f, v1 = s[j][1] * 0.125f;
                float v2 = s[j][2] * 0.125f, v3 = s[j][3] * 0.125f;
                if (needmask) {
                    if (col + 0 > row0) v0 = -1e30f;
                    if (col + 1 > row0) v1 = -1e30f;
                    if (col + 0 > row1) v2 = -1e30f;
                    if (col + 1 > row1) v3 = -1e30f;
                }
                s[j][0] = v0; s[j][1] = v1; s[j][2] = v2; s[j][3] = v3;
                nm0 = fmaxf(nm0, fmaxf(v0, v1));
                nm1 = fmaxf(nm1, fmaxf(v2, v3));
            }
            nm0 = fmaxf(nm0, __shfl_xor_sync(0xffffffffu, nm0, 1));
            nm0 = fmaxf(nm0, __shfl_xor_sync(0xffffffffu, nm0, 2));
            nm1 = fmaxf(nm1, __shfl_xor_sync(0xffffffffu, nm1, 1));
            nm1 = fmaxf(nm1, __shfl_xor_sync(0xffffffffu, nm1, 2));

            const float alpha0 = __expf(mrow0 - nm0);
            const float alpha1 = __expf(mrow1 - nm1);
            mrow0 = nm0; mrow1 = nm1;

            uint32_t pf[4][4];
            float ps0 = 0.f, ps1 = 0.f;
            #pragma unroll
            for (int jp = 0; jp < 4; ++jp) {
                #pragma unroll
                for (int half = 0; half < 2; ++half) {
                    const int j = jp*2 + half;
                    const float p0 = __expf(s[j][0] - nm0);
                    const float p1 = __expf(s[j][1] - nm0);
                    const float p2 = __expf(s[j][2] - nm1);
                    const float p3 = __expf(s[j][3] - nm1);
                    ps0 += p0 + p1; ps1 += p2 + p3;
                    __half2 h01 = __floats2half2_rn(p0, p1);
                    __half2 h23 = __floats2half2_rn(p2, p3);
                    pf[jp][0 + half*2] = *(uint32_t*)&h01;
                    pf[jp][1 + half*2] = *(uint32_t*)&h23;
                }
            }
            ps0 += __shfl_xor_sync(0xffffffffu, ps0, 1);
            ps0 += __shfl_xor_sync(0xffffffffu, ps0, 2);
            ps1 += __shfl_xor_sync(0xffffffffu, ps1, 1);
            ps1 += __shfl_xor_sync(0xffffffffu, ps1, 2);
            lrow0 = lrow0 * alpha0 + ps0;
            lrow1 = lrow1 * alpha1 + ps1;
            #pragma unroll
            for (int j = 0; j < 8; ++j) {
                o[j][0] *= alpha0; o[j][1] *= alpha0;
                o[j][2] *= alpha1; o[j][3] *= alpha1;
            }

            // ---- O += P*V (single pass)
            #pragma unroll
            for (int kat = 0; kat < 4; ++kat) {
                uint32_t vh[4][4];
                #pragma unroll
                for (int jp = 0; jp < 4; ++jp) {
                    const uint32_t roff = (uint32_t)(kat*16 + vRow) * 144
                                        + (uint32_t)(jp*16 + vC8) * 2;
                    LDSM_X4T(vh[jp][0], vh[jp][1], vh[jp][2], vh[jp][3], uV + roff);
                }
                #pragma unroll
                for (int jp = 0; jp < 4; ++jp) {
                    MMA_F16(o[jp*2+0], pf[kat], (&vh[jp][0]));
                    MMA_F16(o[jp*2+1], pf[kat], (&vh[jp][2]));
                }
            }
        }
    }

    // ---- normalize + write fp16 [B,S,D]
    const float inv0 = 1.f / lrow0;
    const float inv1 = 1.f / lrow1;
    const int row0 = q0 + wid*16 + g;
    #pragma unroll
    for (int j = 0; j < 8; ++j) {
        const int col = j*8 + qd*2;
        __half2 v0 = __floats2half2_rn(o[j][0] * inv0, o[j][1] * inv0);
        __half2 v1 = __floats2half2_rn(o[j][2] * inv1, o[j][3] * inv1);
        *(uint32_t*)&g_oh16[(size_t)(b*S_ + row0) * D_ + hoff + col]     = *(uint32_t*)&v0;
        *(uint32_t*)&g_oh16[(size_t)(b*S_ + row0 + 8) * D_ + hoff + col] = *(uint32_t*)&v1;
    }
}

// ---------------------------------------------------------------------------
extern "C" void kernel_launch(void* const* d_in, const int* in_sizes, int n_in,
                              void* d_out, int out_size)
{
    (void)in_sizes; (void)n_in; (void)out_size;
    const float* x  = (const float*)d_in[0];
    const float* Wq = (const float*)d_in[1];
    const float* bq = (const float*)d_in[2];
    const float* Wk = (const float*)d_in[3];
    const float* bk = (const float*)d_in[4];
    const float* Wv = (const float*)d_in[5];
    const float* bv = (const float*)d_in[6];
    const float* Wo = (const float*)d_in[7];
    const float* bo = (const float*)d_in[8];
    float* out = (float*)d_out;

    cudaFuncSetAttribute(mma_gemm, cudaFuncAttributeMaxDynamicSharedMemorySize, GSMEM_BYTES);
    cudaFuncSetAttribute(attn_kernel, cudaFuncAttributeMaxDynamicSharedMemorySize, ASMEM_);

    convert_h<<<(M_*D_/4 + 255)/256, 256>>>((const float4*)x);
    dim3 tg(D_/32, D_/32, 4);
    transpose_w<<<tg, dim3(32, 8)>>>(Wq, Wk, Wv, Wo);

    dim3 gq(D_/128, M_/128, 3);
    mma_gemm<<<gq, 256, GSMEM_BYTES>>>(0, bq, bk, bv, nullptr);

    dim3 ga(S_/128, H_, B_);
    attn_kernel<<<ga, 256, ASMEM_>>>();

    dim3 go(D_/128, M_/128, 1);
    mma_gemm<<<go, 256, GSMEM_BYTES>>>(1, bo, nullptr, nullptr, out);
}

// round 13
// speedup vs baseline: 1.6312x; 1.0971x over previous
#include <cuda_runtime.h>
#include <cuda_bf16.h>
#include <cuda_fp16.h>
#include <cstdint>

#define B_  2
#define S_  2048
#define D_  1024
#define H_  16
#define HD_ 64
#define M_  (B_*S_)   // 4096

// ---------------------------------------------------------------------------
// Scratch (allocation-free rule: static device globals)
// ---------------------------------------------------------------------------
__device__ __half g_xh16[M_*D_];              // fp16(x)
__device__ __half g_oh16[M_*D_];              // fp16(attention out)
__device__ __half g_wth[4][D_*D_];            // W^T fp16 [N,K]

// fp16 q/v (single) and split-fp16 k for tensor attention
__device__ __half g_q16[M_*D_];
__device__ __half g_kh16[M_*D_], g_kl16[M_*D_];
__device__ __half g_v16[M_*D_];

// ---------------------------------------------------------------------------
__device__ __forceinline__ uint32_t smem_u32(const void* p) {
    uint32_t a;
    asm("{ .reg .u64 t; cvta.to.shared.u64 t, %1; cvt.u32.u64 %0, t; }" : "=r"(a) : "l"(p));
    return a;
}

#define CP_ASYNC16(dst, src) \
    asm volatile("cp.async.cg.shared.global [%0], [%1], 16;" :: "r"(dst), "l"(src))
#define CP_COMMIT()  asm volatile("cp.async.commit_group;" ::: "memory")
#define CP_WAIT(n)   asm volatile("cp.async.wait_group %0;" :: "n"(n) : "memory")

#define LDSM_X4(r0, r1, r2, r3, addr) \
    asm volatile("ldmatrix.sync.aligned.m8n8.x4.shared.b16 {%0,%1,%2,%3}, [%4];" \
        : "=r"(r0), "=r"(r1), "=r"(r2), "=r"(r3) : "r"(addr))

#define LDSM_X4T(r0, r1, r2, r3, addr) \
    asm volatile("ldmatrix.sync.aligned.m8n8.x4.trans.shared.b16 {%0,%1,%2,%3}, [%4];" \
        : "=r"(r0), "=r"(r1), "=r"(r2), "=r"(r3) : "r"(addr))

#define MMA_F16(d, a, b) \
    asm volatile("mma.sync.aligned.m16n8k16.row.col.f32.f16.f16.f32 " \
        "{%0,%1,%2,%3}, {%4,%5,%6,%7}, {%8,%9}, {%0,%1,%2,%3};" \
        : "+f"((d)[0]), "+f"((d)[1]), "+f"((d)[2]), "+f"((d)[3]) \
        : "r"((a)[0]), "r"((a)[1]), "r"((a)[2]), "r"((a)[3]), "r"((b)[0]), "r"((b)[1]))

// split two fp32 into (hi fp16x2, lo fp16x2)
__device__ __forceinline__ void split2h(float x, float y, uint32_t& hi, uint32_t& lo) {
    __half2 h = __floats2half2_rn(x, y);
    __half2 l = __floats2half2_rn(x - __half2float(h.x), y - __half2float(h.y));
    hi = *(uint32_t*)&h;
    lo = *(uint32_t*)&l;
}

// ---------------------------------------------------------------------------
// Convert fp32 x -> fp16 g_xh16.
// ---------------------------------------------------------------------------
__global__ void __launch_bounds__(256) convert_h(const float4* __restrict__ xin)
{
    const int i = blockIdx.x * 256 + threadIdx.x;
    const float4 v = xin[i];
    __half2 p0 = __floats2half2_rn(v.x, v.y);
    __half2 p1 = __floats2half2_rn(v.z, v.w);
    uint2 u; u.x = *(uint32_t*)&p0; u.y = *(uint32_t*)&p1;
    ((uint2*)g_xh16)[i] = u;
}

// ---------------------------------------------------------------------------
// Transpose: W[K,N] fp32 -> Wt[N,K] fp16. z selects Wq/Wk/Wv/Wo.
// ---------------------------------------------------------------------------
__global__ void __launch_bounds__(256) transpose_w(
    const float* __restrict__ Wq, const float* __restrict__ Wk,
    const float* __restrict__ Wv, const float* __restrict__ Wo)
{
    const float* W = (blockIdx.z == 0) ? Wq : (blockIdx.z == 1) ? Wk
                   : (blockIdx.z == 2) ? Wv : Wo;
    __half* Thi = g_wth[blockIdx.z];

    __shared__ float tile[32][33];
    const int tx = threadIdx.x, ty = threadIdx.y;
    const int k0 = blockIdx.x * 32, n0 = blockIdx.y * 32;

    #pragma unroll
    for (int j = 0; j < 32; j += 8)
        tile[ty + j][tx] = W[(size_t)(k0 + ty + j) * D_ + n0 + tx];
    __syncthreads();
    #pragma unroll
    for (int j = 0; j < 32; j += 8) {
        float v = tile[tx][ty + j];
        Thi[(size_t)(n0 + ty + j) * D_ + k0 + tx] = __float2half(v);
    }
}

// ---------------------------------------------------------------------------
// Single-pass fp16 GEMM, BK=32 (best measured config, R11).
// mode 0: QKV (z selects); epilogue writes fp16 q/v, split-fp16 k.
// mode 1: out projection -> dout fp32.
// ---------------------------------------------------------------------------
#define BK_   32
#define NT_   (D_ / BK_)
#define TILE_BYTES (128 * 40 * 2)        // 10240 (row stride 80B)
#define STAGE_BYTES (2 * TILE_BYTES)     // A, B
#define GSMEM_BYTES (2 * STAGE_BYTES)    // 40960

extern __shared__ char dsm[];

__global__ void __launch_bounds__(256, 2) mma_gemm(int mode,
    const float* __restrict__ b0, const float* __restrict__ b1,
    const float* __restrict__ b2, float* __restrict__ dout)
{
    const int z = mode ? 3 : blockIdx.z;
    const __half* A   = mode ? g_oh16 : g_xh16;
    const __half* Bh  = g_wth[z];
    const float* bias = mode ? b0 : (z == 0 ? b0 : (z == 1 ? b1 : b2));

    const int tid  = threadIdx.x;
    const int lane = tid & 31;
    const int wid  = tid >> 5;
    const int wm   = (wid & 1) * 64;
    const int wn   = (wid >> 1) * 32;
    const int m0 = blockIdx.y * 128;
    const int n0 = blockIdx.x * 128;

    const uint32_t sb = smem_u32(dsm);

    const int cA = tid * 2, cB = tid * 2 + 1;
    const int rA = cA >> 2, qA = cA & 3;
    const int rB = cB >> 2, qB = cB & 3;

    auto issue = [&](int t) {
        const int kc = t * BK_;
        const uint32_t st = sb + (t & 1) * STAGE_BYTES;
        CP_ASYNC16(st + rA * 80 + qA * 16, A  + (size_t)(m0 + rA) * D_ + kc + qA * 8);
        CP_ASYNC16(st + rB * 80 + qB * 16, A  + (size_t)(m0 + rB) * D_ + kc + qB * 8);
        CP_ASYNC16(st + TILE_BYTES + rA * 80 + qA * 16, Bh + (size_t)(n0 + rA) * D_ + kc + qA * 8);
        CP_ASYNC16(st + TILE_BYTES + rB * 80 + qB * 16, Bh + (size_t)(n0 + rB) * D_ + kc + qB * 8);
        CP_COMMIT();
    };

    float d[4][4][4];
    #pragma unroll
    for (int i = 0; i < 4; ++i)
        #pragma unroll
        for (int j = 0; j < 4; ++j)
            #pragma unroll
            for (int r = 0; r < 4; ++r) d[i][j][r] = 0.f;

    issue(0);

    const int aRow = lane & 15;
    const int aK8  = (lane >> 4) * 8;
    const int bRow = (lane & 7) + ((lane >> 4) & 1) * 8;
    const int bK8  = ((lane >> 3) & 1) * 8;

    for (int t = 0; t < NT_; ++t) {
        if (t + 1 < NT_) { issue(t + 1); CP_WAIT(1); } else { CP_WAIT(0); }
        __syncthreads();

        const uint32_t st = sb + (t & 1) * STAGE_BYTES;
        #pragma unroll
        for (int ks = 0; ks < BK_; ks += 16) {
            uint32_t a[4][4];
            #pragma unroll
            for (int ms = 0; ms < 4; ++ms) {
                uint32_t addr = st + (uint32_t)(wm + ms*16 + aRow) * 80
                              + (uint32_t)(ks + aK8) * 2;
                LDSM_X4(a[ms][0], a[ms][1], a[ms][2], a[ms][3], addr);
            }
            uint32_t bh[4][2];
            #pragma unroll
            for (int np = 0; np < 2; ++np) {
                uint32_t r0, r1, r2, r3;
                uint32_t boff = (uint32_t)(wn + np*16 + bRow) * 80
                              + (uint32_t)(ks + bK8) * 2;
                LDSM_X4(r0, r1, r2, r3, st + TILE_BYTES + boff);
                bh[np*2+0][0] = r0; bh[np*2+0][1] = r1;
                bh[np*2+1][0] = r2; bh[np*2+1][1] = r3;
            }
            #pragma unroll
            for (int ms = 0; ms < 4; ++ms)
                #pragma unroll
                for (int ns = 0; ns < 4; ++ns)
                    MMA_F16(d[ms][ns], a[ms], bh[ns]);
        }
        __syncthreads();
    }

    const int g = lane >> 2, q = lane & 3;
    if (mode == 0) {
        #pragma unroll
        for (int ns = 0; ns < 4; ++ns) {
            const int col = n0 + wn + ns * 8 + q * 2;
            const float2 bv = *(const float2*)&bias[col];
            #pragma unroll
            for (int ms = 0; ms < 4; ++ms) {
                const int row = m0 + wm + ms * 16 + g;
                const float x0 = d[ms][ns][0] + bv.x, y0 = d[ms][ns][1] + bv.y;
                const float x1 = d[ms][ns][2] + bv.x, y1 = d[ms][ns][3] + bv.y;
                if (z == 1) {   // K: split fp16
                    uint32_t h0, l0, h1, l1;
                    split2h(x0, y0, h0, l0);
                    split2h(x1, y1, h1, l1);
                    *(uint32_t*)&g_kh16[(size_t)row * D_ + col]       = h0;
                    *(uint32_t*)&g_kl16[(size_t)row * D_ + col]       = l0;
                    *(uint32_t*)&g_kh16[(size_t)(row + 8) * D_ + col] = h1;
                    *(uint32_t*)&g_kl16[(size_t)(row + 8) * D_ + col] = l1;
                } else {        // Q or V: single fp16
                    __half* Dst = (z == 0) ? g_q16 : g_v16;
                    __half2 h0 = __floats2half2_rn(x0, y0);
                    __half2 h1 = __floats2half2_rn(x1, y1);
                    *(uint32_t*)&Dst[(size_t)row * D_ + col]       = *(uint32_t*)&h0;
                    *(uint32_t*)&Dst[(size_t)(row + 8) * D_ + col] = *(uint32_t*)&h1;
                }
            }
        }
    } else {
        #pragma unroll
        for (int ns = 0; ns < 4; ++ns) {
            const int col = n0 + wn + ns * 8 + q * 2;
            const float2 bv = *(const float2*)&bias[col];
            #pragma unroll
            for (int ms = 0; ms < 4; ++ms) {
                const int row = m0 + wm + ms * 16 + g;
                float2 v0 = { d[ms][ns][0] + bv.x, d[ms][ns][1] + bv.y };
                float2 v1 = { d[ms][ns][2] + bv.x, d[ms][ns][3] + bv.y };
                *(float2*)&dout[(size_t)row * D_ + col]       = v0;
                *(float2*)&dout[(size_t)(row + 8) * D_ + col] = v1;
            }
        }
    }
}

// ---------------------------------------------------------------------------
// Tensor-core flash attention: Q,P,V fp16 single; K split fp16 hi/lo.
//   S = Q*Kh + Q*Kl ; O = P*V.  3-stage ring of {Kh, Kl, V}.  2 CTAs/SM.
// ---------------------------------------------------------------------------
#define AROW_ 72
#define ATB_  (64 * AROW_ * 2)        // 9216
#define ASTG_ (3 * ATB_)              // {Kh, Kl, V} = 27648
#define ASMEM_ (3 * ASTG_)            // 82944

__global__ void __launch_bounds__(256, 2) attn_kernel()
{
    const int qb = (int)(gridDim.x - 1 - blockIdx.x);   // heavy tiles first
    const int h  = blockIdx.y;
    const int b  = blockIdx.z;
    const int q0 = qb * 128;
    const size_t hoff = (size_t)h * HD_;

    const int tid  = threadIdx.x;
    const int lane = tid & 31;
    const int wid  = tid >> 5;
    const int g    = lane >> 2;
    const int qd   = lane & 3;

    const uint32_t sb = smem_u32(dsm);

    const int c0 = tid * 2, c1 = tid * 2 + 1;
    const int r0c = c0 >> 3, q0c = c0 & 7;
    const int r1c = c1 >> 3, q1c = c1 & 7;

    // ---- Q (128x64 fp16) into stage-0 tiles 0,1 (temporary)
    {
        const size_t base0 = (size_t)(b*S_ + q0) * D_ + hoff;
        const size_t base1 = (size_t)(b*S_ + q0 + 64) * D_ + hoff;
        CP_ASYNC16(sb + 0*ATB_ + r0c*144 + q0c*16, g_q16 + base0 + r0c*D_ + q0c*8);
        CP_ASYNC16(sb + 0*ATB_ + r1c*144 + q1c*16, g_q16 + base0 + r1c*D_ + q1c*8);
        CP_ASYNC16(sb + 1*ATB_ + r0c*144 + q0c*16, g_q16 + base1 + r0c*D_ + q0c*8);
        CP_ASYNC16(sb + 1*ATB_ + r1c*144 + q1c*16, g_q16 + base1 + r1c*D_ + q1c*8);
        CP_COMMIT();
    }

    auto issue_tile = [&](int kt) {
        const int stg = (kt + 1) % 3;
        const uint32_t st = sb + stg * ASTG_;
        const size_t base = (size_t)(b*S_ + kt*64) * D_ + hoff;
        const size_t o0 = base + r0c*D_ + q0c*8;
        const size_t o1 = base + r1c*D_ + q1c*8;
        const uint32_t d0 = r0c*144 + q0c*16;
        const uint32_t d1 = r1c*144 + q1c*16;
        CP_ASYNC16(st + 0*ATB_ + d0, g_kh16 + o0);
        CP_ASYNC16(st + 0*ATB_ + d1, g_kh16 + o1);
        CP_ASYNC16(st + 1*ATB_ + d0, g_kl16 + o0);
        CP_ASYNC16(st + 1*ATB_ + d1, g_kl16 + o1);
        CP_ASYNC16(st + 2*ATB_ + d0, g_v16 + o0);
        CP_ASYNC16(st + 2*ATB_ + d1, g_v16 + o1);
        CP_COMMIT();
    };

    issue_tile(0);          // -> stage 1
    CP_WAIT(1);             // Q group done
    __syncthreads();

    // ---- Q fragments (fp16, 16 regs)
    uint32_t qf[4][4];
    {
        const uint32_t qbase = sb + ((wid < 4) ? 0 : 1) * ATB_;
        const int rr = (wid & 3) * 16 + ((lane >> 3) & 1) * 8 + (lane & 7);
        #pragma unroll
        for (int kat = 0; kat < 4; ++kat) {
            const uint32_t koff = (uint32_t)(kat * 16 + ((lane >> 4) & 1) * 8) * 2;
            LDSM_X4(qf[kat][0], qf[kat][1], qf[kat][2], qf[kat][3],
                    qbase + (uint32_t)rr * 144 + koff);
        }
    }

    float o[8][4];
    #pragma unroll
    for (int j = 0; j < 8; ++j)
        #pragma unroll
        for (int r = 0; r < 4; ++r) o[j][r] = 0.f;
    float mrow0 = -1e30f, mrow1 = -1e30f, lrow0 = 0.f, lrow1 = 0.f;

    const int wrow0 = q0 + wid * 16;

    const int kRow = ((lane >> 4) & 1) * 8 + (lane & 7);
    const int kK8  = ((lane >> 3) & 1) * 8;
    const int vRow = ((lane >> 3) & 1) * 8 + (lane & 7);
    const int vC8  = ((lane >> 4) & 1) * 8;

    const int nkt = 2 * (qb + 1);
    for (int kt = 0; kt < nkt; ++kt) {
        const int k0 = kt * 64;
        if (kt + 1 < nkt) { issue_tile(kt + 1); CP_WAIT(1); } else { CP_WAIT(0); }
        __syncthreads();

        const uint32_t st = sb + ((kt + 1) % 3) * ASTG_;
        const uint32_t uKhi = st, uKlo = st + ATB_;
        const uint32_t uV = st + 2*ATB_;

        if (k0 <= wrow0 + 15) {
            // ---- S = Q*Kh + Q*Kl
            float s[8][4];
            #pragma unroll
            for (int j = 0; j < 8; ++j)
                #pragma unroll
                for (int r = 0; r < 4; ++r) s[j][r] = 0.f;

            #pragma unroll
            for (int kat = 0; kat < 4; ++kat) {
                uint32_t kh[4][4];
                #pragma unroll
                for (int jp = 0; jp < 4; ++jp) {
                    const uint32_t roff = (uint32_t)(jp*16 + kRow) * 144
                                        + (uint32_t)(kat*16 + kK8) * 2;
                    LDSM_X4(kh[jp][0], kh[jp][1], kh[jp][2], kh[jp][3], uKhi + roff);
                }
                #pragma unroll
                for (int jp = 0; jp < 4; ++jp) {
                    MMA_F16(s[jp*2+0], qf[kat], (&kh[jp][0]));
                    MMA_F16(s[jp*2+1], qf[kat], (&kh[jp][2]));
                }
                uint32_t kl[4][4];
                #pragma unroll
                for (int jp = 0; jp < 4; ++jp) {
                    const uint32_t roff = (uint32_t)(jp*16 + kRow) * 144
                                        + (uint32_t)(kat*16 + kK8) * 2;
                    LDSM_X4(kl[jp][0], kl[jp][1], kl[jp][2], kl[jp][3], uKlo + roff);
                }
                #pragma unroll
                for (int jp = 0; jp < 4; ++jp) {
                    MMA_F16(s[jp*2+0], qf[kat], (&kl[jp][0]));
                    MMA_F16(s[jp*2+1], qf[kat], (&kl[jp][2]));
                }
            }

            // ---- online softmax
            const int row0 = wrow0 + g;
            const int row1 = row0 + 8;
            const bool needmask = (k0 + 63 > wrow0);
            float nm0 = mrow0, nm1 = mrow1;
            #pragma unroll
            for (int j = 0; j < 8; ++j) {
                const int col = k0 + j*8 + qd*2;
                float v0 = s[j][0] * 0.125f, v1 = s[j][1] * 0.125f;
                float v2 = s[j][2] * 0.125f, v3 = s[j][3] * 0.125f;
                if (needmask) {
                    if (col + 0 > row0) v0 = -1e30f;
                    if (col + 1 > row0) v1 = -1e30f;
                    if (col + 0 > row1) v2 = -1e30f;
                    if (col + 1 > row1) v3 = -1e30f;
                }
                s[j][0] = v0; s[j][1] = v1; s[j][2] = v2; s[j][3] = v3;
                nm0 = fmaxf(nm0, fmaxf(v0, v1));
                nm1 = fmaxf(nm1, fmaxf(v2, v3));
            }
            nm0 = fmaxf(nm0, __shfl_xor_sync(0xffffffffu, nm0, 1));
            nm0 = fmaxf(nm0, __shfl_xor_sync(0xffffffffu, nm0, 2));
            nm1 = fmaxf(nm1, __shfl_xor_sync(0xffffffffu, nm1, 1));
            nm1 = fmaxf(nm1, __shfl_xor_sync(0xffffffffu, nm1, 2));

            const float alpha0 = __expf(mrow0 - nm0);
            const float alpha1 = __expf(mrow1 - nm1);
            mrow0 = nm0; mrow1 = nm1;

            uint32_t pf[4][4];
            float ps0 = 0.f, ps1 = 0.f;
            #pragma unroll
            for (int jp = 0; jp < 4; ++jp) {
                #pragma unroll
                for (int half = 0; half < 2; ++half) {
                    const int j = jp*2 + half;
                    const float p0 = __expf(s[j][0] - nm0);
                    const float p1 = __expf(s[j][1] - nm0);
                    const float p2 = __expf(s[j][2] - nm1);
                    const float p3 = __expf(s[j][3] - nm1);
                    ps0 += p0 + p1; ps1 += p2 + p3;
                    __half2 h01 = __floats2half2_rn(p0, p1);
                    __half2 h23 = __floats2half2_rn(p2, p3);
                    pf[jp][0 + half*2] = *(uint32_t*)&h01;
                    pf[jp][1 + half*2] = *(uint32_t*)&h23;
                }
            }
            ps0 += __shfl_xor_sync(0xffffffffu, ps0, 1);
            ps0 += __shfl_xor_sync(0xffffffffu, ps0, 2);
            ps1 += __shfl_xor_sync(0xffffffffu, ps1, 1);
            ps1 += __shfl_xor_sync(0xffffffffu, ps1, 2);
            lrow0 = lrow0 * alpha0 + ps0;
            lrow1 = lrow1 * alpha1 + ps1;
            #pragma unroll
            for (int j = 0; j < 8; ++j) {
                o[j][0] *= alpha0; o[j][1] *= alpha0;
                o[j][2] *= alpha1; o[j][3] *= alpha1;
            }

            // ---- O += P*V (single pass)
            #pragma unroll
            for (int kat = 0; kat < 4; ++kat) {
                uint32_t vh[4][4];
                #pragma unroll
                for (int jp = 0; jp < 4; ++jp) {
                    const uint32_t roff = (uint32_t)(kat*16 + vRow) * 144
                                        + (uint32_t)(jp*16 + vC8) * 2;
                    LDSM_X4T(vh[jp][0], vh[jp][1], vh[jp][2], vh[jp][3], uV + roff);
                }
                #pragma unroll
                for (int jp = 0; jp < 4; ++jp) {
                    MMA_F16(o[jp*2+0], pf[kat], (&vh[jp][0]));
                    MMA_F16(o[jp*2+1], pf[kat], (&vh[jp][2]));
                }
            }
        }
    }

    // ---- normalize + write fp16 [B,S,D]
    const float inv0 = 1.f / lrow0;
    const float inv1 = 1.f / lrow1;
    const int row0 = q0 + wid*16 + g;
    #pragma unroll
    for (int j = 0; j < 8; ++j) {
        const int col = j*8 + qd*2;
        __half2 v0 = __floats2half2_rn(o[j][0] * inv0, o[j][1] * inv0);
        __half2 v1 = __floats2half2_rn(o[j][2] * inv1, o[j][3] * inv1);
        *(uint32_t*)&g_oh16[(size_t)(b*S_ + row0) * D_ + hoff + col]     = *(uint32_t*)&v0;
        *(uint32_t*)&g_oh16[(size_t)(b*S_ + row0 + 8) * D_ + hoff + col] = *(uint32_t*)&v1;
    }
}

// ---------------------------------------------------------------------------
extern "C" void kernel_launch(void* const* d_in, const int* in_sizes, int n_in,
                              void* d_out, int out_size)
{
    (void)in_sizes; (void)n_in; (void)out_size;
    const float* x  = (const float*)d_in[0];
    const float* Wq = (const float*)d_in[1];
    const float* bq = (const float*)d_in[2];
    const float* Wk = (const float*)d_in[3];
    const float* bk = (const float*)d_in[4];
    const float* Wv = (const float*)d_in[5];
    const float* bv = (const float*)d_in[6];
    const float* Wo = (const float*)d_in[7];
    const float* bo = (const float*)d_in[8];
    float* out = (float*)d_out;

    cudaFuncSetAttribute(mma_gemm, cudaFuncAttributeMaxDynamicSharedMemorySize, GSMEM_BYTES);
    cudaFuncSetAttribute(attn_kernel, cudaFuncAttributeMaxDynamicSharedMemorySize, ASMEM_);

    convert_h<<<(M_*D_/4 + 255)/256, 256>>>((const float4*)x);
    dim3 tg(D_/32, D_/32, 4);
    transpose_w<<<tg, dim3(32, 8)>>>(Wq, Wk, Wv, Wo);

    dim3 gq(D_/128, M_/128, 3);
    mma_gemm<<<gq, 256, GSMEM_BYTES>>>(0, bq, bk, bv, nullptr);

    dim3 ga(S_/128, H_, B_);
    attn_kernel<<<ga, 256, ASMEM_>>>();

    dim3 go(D_/128, M_/128, 1);
    mma_gemm<<<go, 256, GSMEM_BYTES>>>(1, bo, nullptr, nullptr, out);
}

// round 14
// speedup vs baseline: 1.8245x; 1.1185x over previous
#include <cuda_runtime.h>
#include <cuda_bf16.h>
#include <cuda_fp16.h>
#include <cstdint>

#define B_  2
#define S_  2048
#define D_  1024
#define H_  16
#define HD_ 64
#define M_  (B_*S_)   // 4096

// ---------------------------------------------------------------------------
// Scratch (allocation-free rule: static device globals)
// ---------------------------------------------------------------------------
__device__ __half g_xh16[M_*D_];              // fp16(x)
__device__ __half g_oh16[M_*D_];              // fp16(attention out)
__device__ __half g_wth[4][D_*D_];            // W^T fp16 [N,K]

// fp16 q/k/v for tensor attention
__device__ __half g_q16[M_*D_];
__device__ __half g_k16[M_*D_];
__device__ __half g_v16[M_*D_];

// ---------------------------------------------------------------------------
__device__ __forceinline__ uint32_t smem_u32(const void* p) {
    uint32_t a;
    asm("{ .reg .u64 t; cvta.to.shared.u64 t, %1; cvt.u32.u64 %0, t; }" : "=r"(a) : "l"(p));
    return a;
}

#define CP_ASYNC16(dst, src) \
    asm volatile("cp.async.cg.shared.global [%0], [%1], 16;" :: "r"(dst), "l"(src))
#define CP_COMMIT()  asm volatile("cp.async.commit_group;" ::: "memory")
#define CP_WAIT(n)   asm volatile("cp.async.wait_group %0;" :: "n"(n) : "memory")

#define LDSM_X4(r0, r1, r2, r3, addr) \
    asm volatile("ldmatrix.sync.aligned.m8n8.x4.shared.b16 {%0,%1,%2,%3}, [%4];" \
        : "=r"(r0), "=r"(r1), "=r"(r2), "=r"(r3) : "r"(addr))

#define LDSM_X4T(r0, r1, r2, r3, addr) \
    asm volatile("ldmatrix.sync.aligned.m8n8.x4.trans.shared.b16 {%0,%1,%2,%3}, [%4];" \
        : "=r"(r0), "=r"(r1), "=r"(r2), "=r"(r3) : "r"(addr))

#define MMA_F16(d, a, b) \
    asm volatile("mma.sync.aligned.m16n8k16.row.col.f32.f16.f16.f32 " \
        "{%0,%1,%2,%3}, {%4,%5,%6,%7}, {%8,%9}, {%0,%1,%2,%3};" \
        : "+f"((d)[0]), "+f"((d)[1]), "+f"((d)[2]), "+f"((d)[3]) \
        : "r"((a)[0]), "r"((a)[1]), "r"((a)[2]), "r"((a)[3]), "r"((b)[0]), "r"((b)[1]))

// ---------------------------------------------------------------------------
// Convert fp32 x -> fp16 g_xh16.
// ---------------------------------------------------------------------------
__global__ void __launch_bounds__(256) convert_h(const float4* __restrict__ xin)
{
    const int i = blockIdx.x * 256 + threadIdx.x;
    const float4 v = xin[i];
    __half2 p0 = __floats2half2_rn(v.x, v.y);
    __half2 p1 = __floats2half2_rn(v.z, v.w);
    uint2 u; u.x = *(uint32_t*)&p0; u.y = *(uint32_t*)&p1;
    ((uint2*)g_xh16)[i] = u;
}

// ---------------------------------------------------------------------------
// Transpose: W[K,N] fp32 -> Wt[N,K] fp16. z selects Wq/Wk/Wv/Wo.
// ---------------------------------------------------------------------------
__global__ void __launch_bounds__(256) transpose_w(
    const float* __restrict__ Wq, const float* __restrict__ Wk,
    const float* __restrict__ Wv, const float* __restrict__ Wo)
{
    const float* W = (blockIdx.z == 0) ? Wq : (blockIdx.z == 1) ? Wk
                   : (blockIdx.z == 2) ? Wv : Wo;
    __half* Thi = g_wth[blockIdx.z];

    __shared__ float tile[32][33];
    const int tx = threadIdx.x, ty = threadIdx.y;
    const int k0 = blockIdx.x * 32, n0 = blockIdx.y * 32;

    #pragma unroll
    for (int j = 0; j < 32; j += 8)
        tile[ty + j][tx] = W[(size_t)(k0 + ty + j) * D_ + n0 + tx];
    __syncthreads();
    #pragma unroll
    for (int j = 0; j < 32; j += 8) {
        float v = tile[tx][ty + j];
        Thi[(size_t)(n0 + ty + j) * D_ + k0 + tx] = __float2half(v);
    }
}

// ---------------------------------------------------------------------------
// Single-pass fp16 GEMM, BK=32 (best measured config).
// mode 0: QKV (z selects); epilogue writes fp16 q/k/v.
// mode 1: out projection -> dout fp32.
// ---------------------------------------------------------------------------
#define BK_   32
#define NT_   (D_ / BK_)
#define TILE_BYTES (128 * 40 * 2)        // 10240 (row stride 80B)
#define STAGE_BYTES (2 * TILE_BYTES)     // A, B
#define GSMEM_BYTES (2 * STAGE_BYTES)    // 40960

extern __shared__ char dsm[];

__global__ void __launch_bounds__(256, 2) mma_gemm(int mode,
    const float* __restrict__ b0, const float* __restrict__ b1,
    const float* __restrict__ b2, float* __restrict__ dout)
{
    const int z = mode ? 3 : blockIdx.z;
    const __half* A   = mode ? g_oh16 : g_xh16;
    const __half* Bh  = g_wth[z];
    const float* bias = mode ? b0 : (z == 0 ? b0 : (z == 1 ? b1 : b2));

    const int tid  = threadIdx.x;
    const int lane = tid & 31;
    const int wid  = tid >> 5;
    const int wm   = (wid & 1) * 64;
    const int wn   = (wid >> 1) * 32;
    const int m0 = blockIdx.y * 128;
    const int n0 = blockIdx.x * 128;

    const uint32_t sb = smem_u32(dsm);

    const int cA = tid * 2, cB = tid * 2 + 1;
    const int rA = cA >> 2, qA = cA & 3;
    const int rB = cB >> 2, qB = cB & 3;

    auto issue = [&](int t) {
        const int kc = t * BK_;
        const uint32_t st = sb + (t & 1) * STAGE_BYTES;
        CP_ASYNC16(st + rA * 80 + qA * 16, A  + (size_t)(m0 + rA) * D_ + kc + qA * 8);
        CP_ASYNC16(st + rB * 80 + qB * 16, A  + (size_t)(m0 + rB) * D_ + kc + qB * 8);
        CP_ASYNC16(st + TILE_BYTES + rA * 80 + qA * 16, Bh + (size_t)(n0 + rA) * D_ + kc + qA * 8);
        CP_ASYNC16(st + TILE_BYTES + rB * 80 + qB * 16, Bh + (size_t)(n0 + rB) * D_ + kc + qB * 8);
        CP_COMMIT();
    };

    float d[4][4][4];
    #pragma unroll
    for (int i = 0; i < 4; ++i)
        #pragma unroll
        for (int j = 0; j < 4; ++j)
            #pragma unroll
            for (int r = 0; r < 4; ++r) d[i][j][r] = 0.f;

    issue(0);

    const int aRow = lane & 15;
    const int aK8  = (lane >> 4) * 8;
    const int bRow = (lane & 7) + ((lane >> 4) & 1) * 8;
    const int bK8  = ((lane >> 3) & 1) * 8;

    for (int t = 0; t < NT_; ++t) {
        if (t + 1 < NT_) { issue(t + 1); CP_WAIT(1); } else { CP_WAIT(0); }
        __syncthreads();

        const uint32_t st = sb + (t & 1) * STAGE_BYTES;
        #pragma unroll
        for (int ks = 0; ks < BK_; ks += 16) {
            uint32_t a[4][4];
            #pragma unroll
            for (int ms = 0; ms < 4; ++ms) {
                uint32_t addr = st + (uint32_t)(wm + ms*16 + aRow) * 80
                              + (uint32_t)(ks + aK8) * 2;
                LDSM_X4(a[ms][0], a[ms][1], a[ms][2], a[ms][3], addr);
            }
            uint32_t bh[4][2];
            #pragma unroll
            for (int np = 0; np < 2; ++np) {
                uint32_t r0, r1, r2, r3;
                uint32_t boff = (uint32_t)(wn + np*16 + bRow) * 80
                              + (uint32_t)(ks + bK8) * 2;
                LDSM_X4(r0, r1, r2, r3, st + TILE_BYTES + boff);
                bh[np*2+0][0] = r0; bh[np*2+0][1] = r1;
                bh[np*2+1][0] = r2; bh[np*2+1][1] = r3;
            }
            #pragma unroll
            for (int ms = 0; ms < 4; ++ms)
                #pragma unroll
                for (int ns = 0; ns < 4; ++ns)
                    MMA_F16(d[ms][ns], a[ms], bh[ns]);
        }
        __syncthreads();
    }

    const int g = lane >> 2, q = lane & 3;
    if (mode == 0) {
        __half* Dst = (z == 0) ? g_q16 : (z == 1) ? g_k16 : g_v16;
        #pragma unroll
        for (int ns = 0; ns < 4; ++ns) {
            const int col = n0 + wn + ns * 8 + q * 2;
            const float2 bv = *(const float2*)&bias[col];
            #pragma unroll
            for (int ms = 0; ms < 4; ++ms) {
                const int row = m0 + wm + ms * 16 + g;
                __half2 h0 = __floats2half2_rn(d[ms][ns][0] + bv.x, d[ms][ns][1] + bv.y);
                __half2 h1 = __floats2half2_rn(d[ms][ns][2] + bv.x, d[ms][ns][3] + bv.y);
                *(uint32_t*)&Dst[(size_t)row * D_ + col]       = *(uint32_t*)&h0;
                *(uint32_t*)&Dst[(size_t)(row + 8) * D_ + col] = *(uint32_t*)&h1;
            }
        }
    } else {
        #pragma unroll
        for (int ns = 0; ns < 4; ++ns) {
            const int col = n0 + wn + ns * 8 + q * 2;
            const float2 bv = *(const float2*)&bias[col];
            #pragma unroll
            for (int ms = 0; ms < 4; ++ms) {
                const int row = m0 + wm + ms * 16 + g;
                float2 v0 = { d[ms][ns][0] + bv.x, d[ms][ns][1] + bv.y };
                float2 v1 = { d[ms][ns][2] + bv.x, d[ms][ns][3] + bv.y };
                *(float2*)&dout[(size_t)row * D_ + col]       = v0;
                *(float2*)&dout[(size_t)(row + 8) * D_ + col] = v1;
            }
        }
    }
}

// ---------------------------------------------------------------------------
// Tensor-core flash attention: Q,K,V,P all fp16 single-pass.
//   S = Q*K ; O = P*V.  3-stage ring of {K, V}.  2 CTAs/SM.
// ---------------------------------------------------------------------------
#define AROW_ 72
#define ATB_  (64 * AROW_ * 2)        // 9216
#define ASTG_ (2 * ATB_)              // {K, V} = 18432
#define ASMEM_ (3 * ASTG_)            // 55296

__global__ void __launch_bounds__(256, 2) attn_kernel()
{
    const int qb = (int)(gridDim.x - 1 - blockIdx.x);   // heavy tiles first
    const int h  = blockIdx.y;
    const int b  = blockIdx.z;
    const int q0 = qb * 128;
    const size_t hoff = (size_t)h * HD_;

    const int tid  = threadIdx.x;
    const int lane = tid & 31;
    const int wid  = tid >> 5;
    const int g    = lane >> 2;
    const int qd   = lane & 3;

    const uint32_t sb = smem_u32(dsm);

    const int c0 = tid * 2, c1 = tid * 2 + 1;
    const int r0c = c0 >> 3, q0c = c0 & 7;
    const int r1c = c1 >> 3, q1c = c1 & 7;

    // ---- Q (128x64 fp16) into stage-0 tiles 0,1 (temporary; overwritten at kt=1)
    {
        const size_t base0 = (size_t)(b*S_ + q0) * D_ + hoff;
        const size_t base1 = (size_t)(b*S_ + q0 + 64) * D_ + hoff;
        CP_ASYNC16(sb + 0*ATB_ + r0c*144 + q0c*16, g_q16 + base0 + r0c*D_ + q0c*8);
        CP_ASYNC16(sb + 0*ATB_ + r1c*144 + q1c*16, g_q16 + base0 + r1c*D_ + q1c*8);
        CP_ASYNC16(sb + 1*ATB_ + r0c*144 + q0c*16, g_q16 + base1 + r0c*D_ + q0c*8);
        CP_ASYNC16(sb + 1*ATB_ + r1c*144 + q1c*16, g_q16 + base1 + r1c*D_ + q1c*8);
        CP_COMMIT();
    }

    auto issue_tile = [&](int kt) {
        const int stg = (kt + 1) % 3;
        const uint32_t st = sb + stg * ASTG_;
        const size_t base = (size_t)(b*S_ + kt*64) * D_ + hoff;
        const size_t o0 = base + r0c*D_ + q0c*8;
        const size_t o1 = base + r1c*D_ + q1c*8;
        const uint32_t d0 = r0c*144 + q0c*16;
        const uint32_t d1 = r1c*144 + q1c*16;
        CP_ASYNC16(st + 0*ATB_ + d0, g_k16 + o0);
        CP_ASYNC16(st + 0*ATB_ + d1, g_k16 + o1);
        CP_ASYNC16(st + 1*ATB_ + d0, g_v16 + o0);
        CP_ASYNC16(st + 1*ATB_ + d1, g_v16 + o1);
        CP_COMMIT();
    };

    issue_tile(0);          // -> stage 1
    CP_WAIT(1);             // Q group done
    __syncthreads();

    // ---- Q fragments (fp16, 16 regs)
    uint32_t qf[4][4];
    {
        const uint32_t qbase = sb + ((wid < 4) ? 0 : 1) * ATB_;
        const int rr = (wid & 3) * 16 + ((lane >> 3) & 1) * 8 + (lane & 7);
        #pragma unroll
        for (int kat = 0; kat < 4; ++kat) {
            const uint32_t koff = (uint32_t)(kat * 16 + ((lane >> 4) & 1) * 8) * 2;
            LDSM_X4(qf[kat][0], qf[kat][1], qf[kat][2], qf[kat][3],
                    qbase + (uint32_t)rr * 144 + koff);
        }
    }

    float o[8][4];
    #pragma unroll
    for (int j = 0; j < 8; ++j)
        #pragma unroll
        for (int r = 0; r < 4; ++r) o[j][r] = 0.f;
    float mrow0 = -1e30f, mrow1 = -1e30f, lrow0 = 0.f, lrow1 = 0.f;

    const int wrow0 = q0 + wid * 16;

    const int kRow = ((lane >> 4) & 1) * 8 + (lane & 7);
    const int kK8  = ((lane >> 3) & 1) * 8;
    const int vRow = ((lane >> 3) & 1) * 8 + (lane & 7);
    const int vC8  = ((lane >> 4) & 1) * 8;

    const int nkt = 2 * (qb + 1);
    for (int kt = 0; kt < nkt; ++kt) {
        const int k0 = kt * 64;
        if (kt + 1 < nkt) { issue_tile(kt + 1); CP_WAIT(1); } else { CP_WAIT(0); }
        __syncthreads();

        const uint32_t st = sb + ((kt + 1) % 3) * ASTG_;
        const uint32_t uK = st, uV = st + ATB_;

        if (k0 <= wrow0 + 15) {
            // ---- S = Q*K (single pass)
            float s[8][4];
            #pragma unroll
            for (int j = 0; j < 8; ++j)
                #pragma unroll
                for (int r = 0; r < 4; ++r) s[j][r] = 0.f;

            #pragma unroll
            for (int kat = 0; kat < 4; ++kat) {
                uint32_t kh[4][4];
                #pragma unroll
                for (int jp = 0; jp < 4; ++jp) {
                    const uint32_t roff = (uint32_t)(jp*16 + kRow) * 144
                                        + (uint32_t)(kat*16 + kK8) * 2;
                    LDSM_X4(kh[jp][0], kh[jp][1], kh[jp][2], kh[jp][3], uK + roff);
                }
                #pragma unroll
                for (int jp = 0; jp < 4; ++jp) {
                    MMA_F16(s[jp*2+0], qf[kat], (&kh[jp][0]));
                    MMA_F16(s[jp*2+1], qf[kat], (&kh[jp][2]));
                }
            }

            // ---- online softmax
            const int row0 = wrow0 + g;
            const int row1 = row0 + 8;
            const bool needmask = (k0 + 63 > wrow0);
            float nm0 = mrow0, nm1 = mrow1;
            #pragma unroll
            for (int j = 0; j < 8; ++j) {
                const int col = k0 + j*8 + qd*2;
                float v0 = s[j][0] * 0.125f, v1 = s[j][1] * 0.125f;
                float v2 = s[j][2] * 0.125f, v3 = s[j][3] * 0.125f;
                if (needmask) {
                    if (col + 0 > row0) v0 = -1e30f;
                    if (col + 1 > row0) v1 = -1e30f;
                    if (col + 0 > row1) v2 = -1e30f;
                    if (col + 1 > row1) v3 = -1e30f;
                }
                s[j][0] = v0; s[j][1] = v1; s[j][2] = v2; s[j][3] = v3;
                nm0 = fmaxf(nm0, fmaxf(v0, v1));
                nm1 = fmaxf(nm1, fmaxf(v2, v3));
            }
            nm0 = fmaxf(nm0, __shfl_xor_sync(0xffffffffu, nm0, 1));
            nm0 = fmaxf(nm0, __shfl_xor_sync(0xffffffffu, nm0, 2));
            nm1 = fmaxf(nm1, __shfl_xor_sync(0xffffffffu, nm1, 1));
            nm1 = fmaxf(nm1, __shfl_xor_sync(0xffffffffu, nm1, 2));

            const float alpha0 = __expf(mrow0 - nm0);
            const float alpha1 = __expf(mrow1 - nm1);
            mrow0 = nm0; mrow1 = nm1;

            uint32_t pf[4][4];
            float ps0 = 0.f, ps1 = 0.f;
            #pragma unroll
            for (int jp = 0; jp < 4; ++jp) {
                #pragma unroll
                for (int half = 0; half < 2; ++half) {
                    const int j = jp*2 + half;
                    const float p0 = __expf(s[j][0] - nm0);
                    const float p1 = __expf(s[j][1] - nm0);
                    const float p2 = __expf(s[j][2] - nm1);
                    const float p3 = __expf(s[j][3] - nm1);
                    ps0 += p0 + p1; ps1 += p2 + p3;
                    __half2 h01 = __floats2half2_rn(p0, p1);
                    __half2 h23 = __floats2half2_rn(p2, p3);
                    pf[jp][0 + half*2] = *(uint32_t*)&h01;
                    pf[jp][1 + half*2] = *(uint32_t*)&h23;
                }
            }
            ps0 += __shfl_xor_sync(0xffffffffu, ps0, 1);
            ps0 += __shfl_xor_sync(0xffffffffu, ps0, 2);
            ps1 += __shfl_xor_sync(0xffffffffu, ps1, 1);
            ps1 += __shfl_xor_sync(0xffffffffu, ps1, 2);
            lrow0 = lrow0 * alpha0 + ps0;
            lrow1 = lrow1 * alpha1 + ps1;
            #pragma unroll
            for (int j = 0; j < 8; ++j) {
                o[j][0] *= alpha0; o[j][1] *= alpha0;
                o[j][2] *= alpha1; o[j][3] *= alpha1;
            }

            // ---- O += P*V (single pass)
            #pragma unroll
            for (int kat = 0; kat < 4; ++kat) {
                uint32_t vh[4][4];
                #pragma unroll
                for (int jp = 0; jp < 4; ++jp) {
                    const uint32_t roff = (uint32_t)(kat*16 + vRow) * 144
                                        + (uint32_t)(jp*16 + vC8) * 2;
                    LDSM_X4T(vh[jp][0], vh[jp][1], vh[jp][2], vh[jp][3], uV + roff);
                }
                #pragma unroll
                for (int jp = 0; jp < 4; ++jp) {
                    MMA_F16(o[jp*2+0], pf[kat], (&vh[jp][0]));
                    MMA_F16(o[jp*2+1], pf[kat], (&vh[jp][2]));
                }
            }
        }
    }

    // ---- normalize + write fp16 [B,S,D]
    const float inv0 = 1.f / lrow0;
    const float inv1 = 1.f / lrow1;
    const int row0 = q0 + wid*16 + g;
    #pragma unroll
    for (int j = 0; j < 8; ++j) {
        const int col = j*8 + qd*2;
        __half2 v0 = __floats2half2_rn(o[j][0] * inv0, o[j][1] * inv0);
        __half2 v1 = __floats2half2_rn(o[j][2] * inv1, o[j][3] * inv1);
        *(uint32_t*)&g_oh16[(size_t)(b*S_ + row0) * D_ + hoff + col]     = *(uint32_t*)&v0;
        *(uint32_t*)&g_oh16[(size_t)(b*S_ + row0 + 8) * D_ + hoff + col] = *(uint32_t*)&v1;
    }
}

// ---------------------------------------------------------------------------
extern "C" void kernel_launch(void* const* d_in, const int* in_sizes, int n_in,
                              void* d_out, int out_size)
{
    (void)in_sizes; (void)n_in; (void)out_size;
    const float* x  = (const float*)d_in[0];
    const float* Wq = (const float*)d_in[1];
    const float* bq = (const float*)d_in[2];
    const float* Wk = (const float*)d_in[3];
    const float* bk = (const float*)d_in[4];
    const float* Wv = (const float*)d_in[5];
    const float* bv = (const float*)d_in[6];
    const float* Wo = (const float*)d_in[7];
    const float* bo = (const float*)d_in[8];
    float* out = (float*)d_out;

    cudaFuncSetAttribute(mma_gemm, cudaFuncAttributeMaxDynamicSharedMemorySize, GSMEM_BYTES);
    cudaFuncSetAttribute(attn_kernel, cudaFuncAttributeMaxDynamicSharedMemorySize, ASMEM_);

    convert_h<<<(M_*D_/4 + 255)/256, 256>>>((const float4*)x);
    dim3 tg(D_/32, D_/32, 4);
    transpose_w<<<tg, dim3(32, 8)>>>(Wq, Wk, Wv, Wo);

    dim3 gq(D_/128, M_/128, 3);
    mma_gemm<<<gq, 256, GSMEM_BYTES>>>(0, bq, bk, bv, nullptr);

    dim3 ga(S_/128, H_, B_);
    attn_kernel<<<ga, 256, ASMEM_>>>();

    dim3 go(D_/128, M_/128, 1);
    mma_gemm<<<go, 256, GSMEM_BYTES>>>(1, bo, nullptr, nullptr, out);
}

// round 15
// speedup vs baseline: 1.8884x; 1.0351x over previous
#include <cuda_runtime.h>
#include <cuda_bf16.h>
#include <cuda_fp16.h>
#include <cstdint>

#define B_  2
#define S_  2048
#define D_  1024
#define H_  16
#define HD_ 64
#define M_  (B_*S_)   // 4096

// scale folded into Q: 1/sqrt(64) * log2(e)
#define QSCALE_ (0.125f * 1.4426950408889634f)

// ---------------------------------------------------------------------------
// Scratch (allocation-free rule: static device globals)
// ---------------------------------------------------------------------------
__device__ __half g_xh16[M_*D_];              // fp16(x)
__device__ __half g_oh16[M_*D_];              // fp16(attention out)
__device__ __half g_wth[4][D_*D_];            // W^T fp16 [N,K]

// fp16 q/k/v for tensor attention (q pre-scaled by QSCALE_)
__device__ __half g_q16[M_*D_];
__device__ __half g_k16[M_*D_];
__device__ __half g_v16[M_*D_];

// ---------------------------------------------------------------------------
__device__ __forceinline__ uint32_t smem_u32(const void* p) {
    uint32_t a;
    asm("{ .reg .u64 t; cvta.to.shared.u64 t, %1; cvt.u32.u64 %0, t; }" : "=r"(a) : "l"(p));
    return a;
}

#define CP_ASYNC16(dst, src) \
    asm volatile("cp.async.cg.shared.global [%0], [%1], 16;" :: "r"(dst), "l"(src))
#define CP_COMMIT()  asm volatile("cp.async.commit_group;" ::: "memory")
#define CP_WAIT(n)   asm volatile("cp.async.wait_group %0;" :: "n"(n) : "memory")

#define LDSM_X4(r0, r1, r2, r3, addr) \
    asm volatile("ldmatrix.sync.aligned.m8n8.x4.shared.b16 {%0,%1,%2,%3}, [%4];" \
        : "=r"(r0), "=r"(r1), "=r"(r2), "=r"(r3) : "r"(addr))

#define LDSM_X4T(r0, r1, r2, r3, addr) \
    asm volatile("ldmatrix.sync.aligned.m8n8.x4.trans.shared.b16 {%0,%1,%2,%3}, [%4];" \
        : "=r"(r0), "=r"(r1), "=r"(r2), "=r"(r3) : "r"(addr))

#define MMA_F16(d, a, b) \
    asm volatile("mma.sync.aligned.m16n8k16.row.col.f32.f16.f16.f32 " \
        "{%0,%1,%2,%3}, {%4,%5,%6,%7}, {%8,%9}, {%0,%1,%2,%3};" \
        : "+f"((d)[0]), "+f"((d)[1]), "+f"((d)[2]), "+f"((d)[3]) \
        : "r"((a)[0]), "r"((a)[1]), "r"((a)[2]), "r"((a)[3]), "r"((b)[0]), "r"((b)[1]))

// ---------------------------------------------------------------------------
// Convert fp32 x -> fp16 g_xh16.
// ---------------------------------------------------------------------------
__global__ void __launch_bounds__(256) convert_h(const float4* __restrict__ xin)
{
    const int i = blockIdx.x * 256 + threadIdx.x;
    const float4 v = xin[i];
    __half2 p0 = __floats2half2_rn(v.x, v.y);
    __half2 p1 = __floats2half2_rn(v.z, v.w);
    uint2 u; u.x = *(uint32_t*)&p0; u.y = *(uint32_t*)&p1;
    ((uint2*)g_xh16)[i] = u;
}

// ---------------------------------------------------------------------------
// Transpose: W[K,N] fp32 -> Wt[N,K] fp16. z selects Wq/Wk/Wv/Wo.
// ---------------------------------------------------------------------------
__global__ void __launch_bounds__(256) transpose_w(
    const float* __restrict__ Wq, const float* __restrict__ Wk,
    const float* __restrict__ Wv, const float* __restrict__ Wo)
{
    const float* W = (blockIdx.z == 0) ? Wq : (blockIdx.z == 1) ? Wk
                   : (blockIdx.z == 2) ? Wv : Wo;
    __half* Thi = g_wth[blockIdx.z];

    __shared__ float tile[32][33];
    const int tx = threadIdx.x, ty = threadIdx.y;
    const int k0 = blockIdx.x * 32, n0 = blockIdx.y * 32;

    #pragma unroll
    for (int j = 0; j < 32; j += 8)
        tile[ty + j][tx] = W[(size_t)(k0 + ty + j) * D_ + n0 + tx];
    __syncthreads();
    #pragma unroll
    for (int j = 0; j < 32; j += 8) {
        float v = tile[tx][ty + j];
        Thi[(size_t)(n0 + ty + j) * D_ + k0 + tx] = __float2half(v);
    }
}

// ---------------------------------------------------------------------------
// Single-pass fp16 GEMM, BK=32 (best measured config).
// mode 0: QKV (z selects); epilogue writes fp16 q/k/v (q pre-scaled).
// mode 1: out projection -> dout fp32.
// ---------------------------------------------------------------------------
#define BK_   32
#define NT_   (D_ / BK_)
#define TILE_BYTES (128 * 40 * 2)        // 10240 (row stride 80B)
#define STAGE_BYTES (2 * TILE_BYTES)     // A, B
#define GSMEM_BYTES (2 * STAGE_BYTES)    // 40960

extern __shared__ char dsm[];

__global__ void __launch_bounds__(256, 2) mma_gemm(int mode,
    const float* __restrict__ b0, const float* __restrict__ b1,
    const float* __restrict__ b2, float* __restrict__ dout)
{
    const int z = mode ? 3 : blockIdx.z;
    const __half* A   = mode ? g_oh16 : g_xh16;
    const __half* Bh  = g_wth[z];
    const float* bias = mode ? b0 : (z == 0 ? b0 : (z == 1 ? b1 : b2));

    const int tid  = threadIdx.x;
    const int lane = tid & 31;
    const int wid  = tid >> 5;
    const int wm   = (wid & 1) * 64;
    const int wn   = (wid >> 1) * 32;
    const int m0 = blockIdx.y * 128;
    const int n0 = blockIdx.x * 128;

    const uint32_t sb = smem_u32(dsm);

    const int cA = tid * 2, cB = tid * 2 + 1;
    const int rA = cA >> 2, qA = cA & 3;
    const int rB = cB >> 2, qB = cB & 3;

    auto issue = [&](int t) {
        const int kc = t * BK_;
        const uint32_t st = sb + (t & 1) * STAGE_BYTES;
        CP_ASYNC16(st + rA * 80 + qA * 16, A  + (size_t)(m0 + rA) * D_ + kc + qA * 8);
        CP_ASYNC16(st + rB * 80 + qB * 16, A  + (size_t)(m0 + rB) * D_ + kc + qB * 8);
        CP_ASYNC16(st + TILE_BYTES + rA * 80 + qA * 16, Bh + (size_t)(n0 + rA) * D_ + kc + qA * 8);
        CP_ASYNC16(st + TILE_BYTES + rB * 80 + qB * 16, Bh + (size_t)(n0 + rB) * D_ + kc + qB * 8);
        CP_COMMIT();
    };

    float d[4][4][4];
    #pragma unroll
    for (int i = 0; i < 4; ++i)
        #pragma unroll
        for (int j = 0; j < 4; ++j)
            #pragma unroll
            for (int r = 0; r < 4; ++r) d[i][j][r] = 0.f;

    issue(0);

    const int aRow = lane & 15;
    const int aK8  = (lane >> 4) * 8;
    const int bRow = (lane & 7) + ((lane >> 4) & 1) * 8;
    const int bK8  = ((lane >> 3) & 1) * 8;

    for (int t = 0; t < NT_; ++t) {
        if (t + 1 < NT_) { issue(t + 1); CP_WAIT(1); } else { CP_WAIT(0); }
        __syncthreads();

        const uint32_t st = sb + (t & 1) * STAGE_BYTES;
        #pragma unroll
        for (int ks = 0; ks < BK_; ks += 16) {
            uint32_t a[4][4];
            #pragma unroll
            for (int ms = 0; ms < 4; ++ms) {
                uint32_t addr = st + (uint32_t)(wm + ms*16 + aRow) * 80
                              + (uint32_t)(ks + aK8) * 2;
                LDSM_X4(a[ms][0], a[ms][1], a[ms][2], a[ms][3], addr);
            }
            uint32_t bh[4][2];
            #pragma unroll
            for (int np = 0; np < 2; ++np) {
                uint32_t r0, r1, r2, r3;
                uint32_t boff = (uint32_t)(wn + np*16 + bRow) * 80
                              + (uint32_t)(ks + bK8) * 2;
                LDSM_X4(r0, r1, r2, r3, st + TILE_BYTES + boff);
                bh[np*2+0][0] = r0; bh[np*2+0][1] = r1;
                bh[np*2+1][0] = r2; bh[np*2+1][1] = r3;
            }
            #pragma unroll
            for (int ms = 0; ms < 4; ++ms)
                #pragma unroll
                for (int ns = 0; ns < 4; ++ns)
                    MMA_F16(d[ms][ns], a[ms], bh[ns]);
        }
        __syncthreads();
    }

    const int g = lane >> 2, q = lane & 3;
    if (mode == 0) {
        __half* Dst = (z == 0) ? g_q16 : (z == 1) ? g_k16 : g_v16;
        const float sc = (z == 0) ? QSCALE_ : 1.0f;
        #pragma unroll
        for (int ns = 0; ns < 4; ++ns) {
            const int col = n0 + wn + ns * 8 + q * 2;
            const float2 bv = *(const float2*)&bias[col];
            #pragma unroll
            for (int ms = 0; ms < 4; ++ms) {
                const int row = m0 + wm + ms * 16 + g;
                __half2 h0 = __floats2half2_rn((d[ms][ns][0] + bv.x) * sc,
                                               (d[ms][ns][1] + bv.y) * sc);
                __half2 h1 = __floats2half2_rn((d[ms][ns][2] + bv.x) * sc,
                                               (d[ms][ns][3] + bv.y) * sc);
                *(uint32_t*)&Dst[(size_t)row * D_ + col]       = *(uint32_t*)&h0;
                *(uint32_t*)&Dst[(size_t)(row + 8) * D_ + col] = *(uint32_t*)&h1;
            }
        }
    } else {
        #pragma unroll
        for (int ns = 0; ns < 4; ++ns) {
            const int col = n0 + wn + ns * 8 + q * 2;
            const float2 bv = *(const float2*)&bias[col];
            #pragma unroll
            for (int ms = 0; ms < 4; ++ms) {
                const int row = m0 + wm + ms * 16 + g;
                float2 v0 = { d[ms][ns][0] + bv.x, d[ms][ns][1] + bv.y };
                float2 v1 = { d[ms][ns][2] + bv.x, d[ms][ns][3] + bv.y };
                *(float2*)&dout[(size_t)row * D_ + col]       = v0;
                *(float2*)&dout[(size_t)(row + 8) * D_ + col] = v1;
            }
        }
    }
}

// ---------------------------------------------------------------------------
// Tensor-core flash attention: Q,K,V,P all fp16 single-pass; scores in log2
// domain (scale folded into Q), exp2f softmax.
//   S = Q*K ; O = P*V.  3-stage ring of {K, V}.  2 CTAs/SM.
// ---------------------------------------------------------------------------
#define AROW_ 72
#define ATB_  (64 * AROW_ * 2)        // 9216
#define ASTG_ (2 * ATB_)              // {K, V} = 18432
#define ASMEM_ (3 * ASTG_)            // 55296

__global__ void __launch_bounds__(256, 2) attn_kernel()
{
    const int qb = (int)(gridDim.x - 1 - blockIdx.x);   // heavy tiles first
    const int h  = blockIdx.y;
    const int b  = blockIdx.z;
    const int q0 = qb * 128;
    const size_t hoff = (size_t)h * HD_;

    const int tid  = threadIdx.x;
    const int lane = tid & 31;
    const int wid  = tid >> 5;
    const int g    = lane >> 2;
    const int qd   = lane & 3;

    const uint32_t sb = smem_u32(dsm);

    const int c0 = tid * 2, c1 = tid * 2 + 1;
    const int r0c = c0 >> 3, q0c = c0 & 7;
    const int r1c = c1 >> 3, q1c = c1 & 7;

    // ---- Q (128x64 fp16, pre-scaled) into stage-0 tiles 0,1 (temporary)
    {
        const size_t base0 = (size_t)(b*S_ + q0) * D_ + hoff;
        const size_t base1 = (size_t)(b*S_ + q0 + 64) * D_ + hoff;
        CP_ASYNC16(sb + 0*ATB_ + r0c*144 + q0c*16, g_q16 + base0 + r0c*D_ + q0c*8);
        CP_ASYNC16(sb + 0*ATB_ + r1c*144 + q1c*16, g_q16 + base0 + r1c*D_ + q1c*8);
        CP_ASYNC16(sb + 1*ATB_ + r0c*144 + q0c*16, g_q16 + base1 + r0c*D_ + q0c*8);
        CP_ASYNC16(sb + 1*ATB_ + r1c*144 + q1c*16, g_q16 + base1 + r1c*D_ + q1c*8);
        CP_COMMIT();
    }

    auto issue_tile = [&](int kt) {
        const int stg = (kt + 1) % 3;
        const uint32_t st = sb + stg * ASTG_;
        const size_t base = (size_t)(b*S_ + kt*64) * D_ + hoff;
        const size_t o0 = base + r0c*D_ + q0c*8;
        const size_t o1 = base + r1c*D_ + q1c*8;
        const uint32_t d0 = r0c*144 + q0c*16;
        const uint32_t d1 = r1c*144 + q1c*16;
        CP_ASYNC16(st + 0*ATB_ + d0, g_k16 + o0);
        CP_ASYNC16(st + 0*ATB_ + d1, g_k16 + o1);
        CP_ASYNC16(st + 1*ATB_ + d0, g_v16 + o0);
        CP_ASYNC16(st + 1*ATB_ + d1, g_v16 + o1);
        CP_COMMIT();
    };

    issue_tile(0);          // -> stage 1
    CP_WAIT(1);             // Q group done
    __syncthreads();

    // ---- Q fragments (fp16, 16 regs)
    uint32_t qf[4][4];
    {
        const uint32_t qbase = sb + ((wid < 4) ? 0 : 1) * ATB_;
        const int rr = (wid & 3) * 16 + ((lane >> 3) & 1) * 8 + (lane & 7);
        #pragma unroll
        for (int kat = 0; kat < 4; ++kat) {
            const uint32_t koff = (uint32_t)(kat * 16 + ((lane >> 4) & 1) * 8) * 2;
            LDSM_X4(qf[kat][0], qf[kat][1], qf[kat][2], qf[kat][3],
                    qbase + (uint32_t)rr * 144 + koff);
        }
    }

    float o[8][4];
    #pragma unroll
    for (int j = 0; j < 8; ++j)
        #pragma unroll
        for (int r = 0; r < 4; ++r) o[j][r] = 0.f;
    float mrow0 = -1e30f, mrow1 = -1e30f, lrow0 = 0.f, lrow1 = 0.f;

    const int wrow0 = q0 + wid * 16;

    const int kRow = ((lane >> 4) & 1) * 8 + (lane & 7);
    const int kK8  = ((lane >> 3) & 1) * 8;
    const int vRow = ((lane >> 3) & 1) * 8 + (lane & 7);
    const int vC8  = ((lane >> 4) & 1) * 8;

    const int nkt = 2 * (qb + 1);
    for (int kt = 0; kt < nkt; ++kt) {
        const int k0 = kt * 64;
        if (kt + 1 < nkt) { issue_tile(kt + 1); CP_WAIT(1); } else { CP_WAIT(0); }
        __syncthreads();

        const uint32_t st = sb + ((kt + 1) % 3) * ASTG_;
        const uint32_t uK = st, uV = st + ATB_;

        if (k0 <= wrow0 + 15) {
            // ---- S = Q*K (single pass; scores already in log2 domain)
            float s[8][4];
            #pragma unroll
            for (int j = 0; j < 8; ++j)
                #pragma unroll
                for (int r = 0; r < 4; ++r) s[j][r] = 0.f;

            #pragma unroll
            for (int kat = 0; kat < 4; ++kat) {
                uint32_t kh[4][4];
                #pragma unroll
                for (int jp = 0; jp < 4; ++jp) {
                    const uint32_t roff = (uint32_t)(jp*16 + kRow) * 144
                                        + (uint32_t)(kat*16 + kK8) * 2;
                    LDSM_X4(kh[jp][0], kh[jp][1], kh[jp][2], kh[jp][3], uK + roff);
                }
                #pragma unroll
                for (int jp = 0; jp < 4; ++jp) {
                    MMA_F16(s[jp*2+0], qf[kat], (&kh[jp][0]));
                    MMA_F16(s[jp*2+1], qf[kat], (&kh[jp][2]));
                }
            }

            // ---- online softmax (log2 domain)
            const int row0 = wrow0 + g;
            const int row1 = row0 + 8;
            const bool needmask = (k0 + 63 > wrow0);
            float nm0 = mrow0, nm1 = mrow1;
            #pragma unroll
            for (int j = 0; j < 8; ++j) {
                const int col = k0 + j*8 + qd*2;
                float v0 = s[j][0], v1 = s[j][1];
                float v2 = s[j][2], v3 = s[j][3];
                if (needmask) {
                    if (col + 0 > row0) v0 = -1e30f;
                    if (col + 1 > row0) v1 = -1e30f;
                    if (col + 0 > row1) v2 = -1e30f;
                    if (col + 1 > row1) v3 = -1e30f;
                }
                s[j][0] = v0; s[j][1] = v1; s[j][2] = v2; s[j][3] = v3;
                nm0 = fmaxf(nm0, fmaxf(v0, v1));
                nm1 = fmaxf(nm1, fmaxf(v2, v3));
            }
            nm0 = fmaxf(nm0, __shfl_xor_sync(0xffffffffu, nm0, 1));
            nm0 = fmaxf(nm0, __shfl_xor_sync(0xffffffffu, nm0, 2));
            nm1 = fmaxf(nm1, __shfl_xor_sync(0xffffffffu, nm1, 1));
            nm1 = fmaxf(nm1, __shfl_xor_sync(0xffffffffu, nm1, 2));

            const float alpha0 = exp2f(mrow0 - nm0);
            const float alpha1 = exp2f(mrow1 - nm1);
            mrow0 = nm0; mrow1 = nm1;

            uint32_t pf[4][4];
            float ps0 = 0.f, ps1 = 0.f;
            #pragma unroll
            for (int jp = 0; jp < 4; ++jp) {
                #pragma unroll
                for (int half = 0; half < 2; ++half) {
                    const int j = jp*2 + half;
                    const float p0 = exp2f(s[j][0] - nm0);
                    const float p1 = exp2f(s[j][1] - nm0);
                    const float p2 = exp2f(s[j][2] - nm1);
                    const float p3 = exp2f(s[j][3] - nm1);
                    ps0 += p0 + p1; ps1 += p2 + p3;
                    __half2 h01 = __floats2half2_rn(p0, p1);
                    __half2 h23 = __floats2half2_rn(p2, p3);
                    pf[jp][0 + half*2] = *(uint32_t*)&h01;
                    pf[jp][1 + half*2] = *(uint32_t*)&h23;
                }
            }
            ps0 += __shfl_xor_sync(0xffffffffu, ps0, 1);
            ps0 += __shfl_xor_sync(0xffffffffu, ps0, 2);
            ps1 += __shfl_xor_sync(0xffffffffu, ps1, 1);
            ps1 += __shfl_xor_sync(0xffffffffu, ps1, 2);
            lrow0 = lrow0 * alpha0 + ps0;
            lrow1 = lrow1 * alpha1 + ps1;
            #pragma unroll
            for (int j = 0; j < 8; ++j) {
                o[j][0] *= alpha0; o[j][1] *= alpha0;
                o[j][2] *= alpha1; o[j][3] *= alpha1;
            }

            // ---- O += P*V (single pass)
            #pragma unroll
            for (int kat = 0; kat < 4; ++kat) {
                uint32_t vh[4][4];
                #pragma unroll
                for (int jp = 0; jp < 4; ++jp) {
                    const uint32_t roff = (uint32_t)(kat*16 + vRow) * 144
                                        + (uint32_t)(jp*16 + vC8) * 2;
                    LDSM_X4T(vh[jp][0], vh[jp][1], vh[jp][2], vh[jp][3], uV + roff);
                }
                #pragma unroll
                for (int jp = 0; jp < 4; ++jp) {
                    MMA_F16(o[jp*2+0], pf[kat], (&vh[jp][0]));
                    MMA_F16(o[jp*2+1], pf[kat], (&vh[jp][2]));
                }
            }
        }
    }

    // ---- normalize + write fp16 [B,S,D]
    const float inv0 = 1.f / lrow0;
    const float inv1 = 1.f / lrow1;
    const int row0 = q0 + wid*16 + g;
    #pragma unroll
    for (int j = 0; j < 8; ++j) {
        const int col = j*8 + qd*2;
        __half2 v0 = __floats2half2_rn(o[j][0] * inv0, o[j][1] * inv0);
        __half2 v1 = __floats2half2_rn(o[j][2] * inv1, o[j][3] * inv1);
        *(uint32_t*)&g_oh16[(size_t)(b*S_ + row0) * D_ + hoff + col]     = *(uint32_t*)&v0;
        *(uint32_t*)&g_oh16[(size_t)(b*S_ + row0 + 8) * D_ + hoff + col] = *(uint32_t*)&v1;
    }
}

// ---------------------------------------------------------------------------
extern "C" void kernel_launch(void* const* d_in, const int* in_sizes, int n_in,
                              void* d_out, int out_size)
{
    (void)in_sizes; (void)n_in; (void)out_size;
    const float* x  = (const float*)d_in[0];
    const float* Wq = (const float*)d_in[1];
    const float* bq = (const float*)d_in[2];
    const float* Wk = (const float*)d_in[3];
    const float* bk = (const float*)d_in[4];
    const float* Wv = (const float*)d_in[5];
    const float* bv = (const float*)d_in[6];
    const float* Wo = (const float*)d_in[7];
    const float* bo = (const float*)d_in[8];
    float* out = (float*)d_out;

    cudaFuncSetAttribute(mma_gemm, cudaFuncAttributeMaxDynamicSharedMemorySize, GSMEM_BYTES);
    cudaFuncSetAttribute(attn_kernel, cudaFuncAttributeMaxDynamicSharedMemorySize, ASMEM_);

    convert_h<<<(M_*D_/4 + 255)/256, 256>>>((const float4*)x);
    dim3 tg(D_/32, D_/32, 4);
    transpose_w<<<tg, dim3(32, 8)>>>(Wq, Wk, Wv, Wo);

    dim3 gq(D_/128, M_/128, 3);
    mma_gemm<<<gq, 256, GSMEM_BYTES>>>(0, bq, bk, bv, nullptr);

    dim3 ga(S_/128, H_, B_);
    attn_kernel<<<ga, 256, ASMEM_>>>();

    dim3 go(D_/128, M_/128, 1);
    mma_gemm<<<go, 256, GSMEM_BYTES>>>(1, bo, nullptr, nullptr, out);
}

// round 16
// speedup vs baseline: 1.9791x; 1.0480x over previous
#include <cuda_runtime.h>
#include <cuda_bf16.h>
#include <cuda_fp16.h>
#include <cstdint>

#define B_  2
#define S_  2048
#define D_  1024
#define H_  16
#define HD_ 64
#define M_  (B_*S_)   // 4096

// scale folded into Q: 1/sqrt(64) * log2(e)
#define QSCALE_ (0.125f * 1.4426950408889634f)

// ---------------------------------------------------------------------------
// Scratch (allocation-free rule: static device globals)
// ---------------------------------------------------------------------------
__device__ __half g_xh16[M_*D_];              // fp16(x)
__device__ __half g_oh16[M_*D_];              // fp16(attention out)
__device__ __half g_w16[4][D_*D_];            // W fp16, natural [K,N]

// fp16 q/k/v for tensor attention (q pre-scaled by QSCALE_)
__device__ __half g_q16[M_*D_];
__device__ __half g_k16[M_*D_];
__device__ __half g_v16[M_*D_];

// ---------------------------------------------------------------------------
__device__ __forceinline__ uint32_t smem_u32(const void* p) {
    uint32_t a;
    asm("{ .reg .u64 t; cvta.to.shared.u64 t, %1; cvt.u32.u64 %0, t; }" : "=r"(a) : "l"(p));
    return a;
}

#define CP_ASYNC16(dst, src) \
    asm volatile("cp.async.cg.shared.global [%0], [%1], 16;" :: "r"(dst), "l"(src))
#define CP_COMMIT()  asm volatile("cp.async.commit_group;" ::: "memory")
#define CP_WAIT(n)   asm volatile("cp.async.wait_group %0;" :: "n"(n) : "memory")

#define LDSM_X4(r0, r1, r2, r3, addr) \
    asm volatile("ldmatrix.sync.aligned.m8n8.x4.shared.b16 {%0,%1,%2,%3}, [%4];" \
        : "=r"(r0), "=r"(r1), "=r"(r2), "=r"(r3) : "r"(addr))

#define LDSM_X4T(r0, r1, r2, r3, addr) \
    asm volatile("ldmatrix.sync.aligned.m8n8.x4.trans.shared.b16 {%0,%1,%2,%3}, [%4];" \
        : "=r"(r0), "=r"(r1), "=r"(r2), "=r"(r3) : "r"(addr))

#define MMA_F16(d, a, b) \
    asm volatile("mma.sync.aligned.m16n8k16.row.col.f32.f16.f16.f32 " \
        "{%0,%1,%2,%3}, {%4,%5,%6,%7}, {%8,%9}, {%0,%1,%2,%3};" \
        : "+f"((d)[0]), "+f"((d)[1]), "+f"((d)[2]), "+f"((d)[3]) \
        : "r"((a)[0]), "r"((a)[1]), "r"((a)[2]), "r"((a)[3]), "r"((b)[0]), "r"((b)[1]))

// ---------------------------------------------------------------------------
// Convert fp32 x -> fp16 g_xh16.
// ---------------------------------------------------------------------------
__global__ void __launch_bounds__(256) convert_h(const float4* __restrict__ xin)
{
    const int i = blockIdx.x * 256 + threadIdx.x;
    const float4 v = xin[i];
    __half2 p0 = __floats2half2_rn(v.x, v.y);
    __half2 p1 = __floats2half2_rn(v.z, v.w);
    uint2 u; u.x = *(uint32_t*)&p0; u.y = *(uint32_t*)&p1;
    ((uint2*)g_xh16)[i] = u;
}

// ---------------------------------------------------------------------------
// Convert weights fp32 [K,N] -> fp16 [K,N] (no transpose). y selects matrix.
// ---------------------------------------------------------------------------
__global__ void __launch_bounds__(256) convert_w(
    const float* __restrict__ Wq, const float* __restrict__ Wk,
    const float* __restrict__ Wv, const float* __restrict__ Wo)
{
    const float* W = (blockIdx.y == 0) ? Wq : (blockIdx.y == 1) ? Wk
                   : (blockIdx.y == 2) ? Wv : Wo;
    const int i = blockIdx.x * 256 + threadIdx.x;     // float4 index
    const float4 v = ((const float4*)W)[i];
    __half2 p0 = __floats2half2_rn(v.x, v.y);
    __half2 p1 = __floats2half2_rn(v.z, v.w);
    uint2 u; u.x = *(uint32_t*)&p0; u.y = *(uint32_t*)&p1;
    ((uint2*)g_w16[blockIdx.y])[i] = u;
}

// ---------------------------------------------------------------------------
// Single-pass fp16 GEMM, BK=32. W consumed in natural [K,N] via ldmatrix.trans.
// mode 0: QKV (z selects); epilogue writes fp16 q/k/v (q pre-scaled).
// mode 1: out projection -> dout fp32.
// ---------------------------------------------------------------------------
#define BK_   32
#define NT_   (D_ / BK_)
#define ATILE_ (128 * 80)                // A: 128 rows x 80B = 10240
#define BROWB_ 272                       // B row stride: 256B + 16 pad
#define BTILE_ (32 * BROWB_)             // B: 32 k-rows x 272B = 8704
#define STAGE_BYTES (ATILE_ + BTILE_)    // 18944
#define GSMEM_BYTES (2 * STAGE_BYTES)    // 37888

extern __shared__ char dsm[];

__global__ void __launch_bounds__(256, 2) mma_gemm(int mode,
    const float* __restrict__ b0, const float* __restrict__ b1,
    const float* __restrict__ b2, float* __restrict__ dout)
{
    const int z = mode ? 3 : blockIdx.z;
    const __half* A   = mode ? g_oh16 : g_xh16;
    const __half* Bw  = g_w16[z];
    const float* bias = mode ? b0 : (z == 0 ? b0 : (z == 1 ? b1 : b2));

    const int tid  = threadIdx.x;
    const int lane = tid & 31;
    const int wid  = tid >> 5;
    const int wm   = (wid & 1) * 64;
    const int wn   = (wid >> 1) * 32;
    const int m0 = blockIdx.y * 128;
    const int n0 = blockIdx.x * 128;

    const uint32_t sb = smem_u32(dsm);

    // A staging: 2 x 16B chunks per thread (128 rows x 4 chunks)
    const int cA = tid * 2, cB = tid * 2 + 1;
    const int rA = cA >> 2, qA = cA & 3;
    const int rB = cB >> 2, qB = cB & 3;
    // B staging: 2 x 16B chunks per thread (32 k-rows x 16 chunks)
    const int wb0 = tid * 2, wb1 = tid * 2 + 1;
    const int br0 = wb0 >> 4, bq0 = wb0 & 15;
    const int br1 = wb1 >> 4, bq1 = wb1 & 15;

    auto issue = [&](int t) {
        const int kc = t * BK_;
        const uint32_t st = sb + (t & 1) * STAGE_BYTES;
        CP_ASYNC16(st + rA * 80 + qA * 16, A + (size_t)(m0 + rA) * D_ + kc + qA * 8);
        CP_ASYNC16(st + rB * 80 + qB * 16, A + (size_t)(m0 + rB) * D_ + kc + qB * 8);
        CP_ASYNC16(st + ATILE_ + br0 * BROWB_ + bq0 * 16,
                   Bw + (size_t)(kc + br0) * D_ + n0 + bq0 * 8);
        CP_ASYNC16(st + ATILE_ + br1 * BROWB_ + bq1 * 16,
                   Bw + (size_t)(kc + br1) * D_ + n0 + bq1 * 8);
        CP_COMMIT();
    };

    float d[4][4][4];
    #pragma unroll
    for (int i = 0; i < 4; ++i)
        #pragma unroll
        for (int j = 0; j < 4; ++j)
            #pragma unroll
            for (int r = 0; r < 4; ++r) d[i][j][r] = 0.f;

    issue(0);

    const int aRow = lane & 15;
    const int aK8  = (lane >> 4) * 8;
    const int wRow = ((lane >> 3) & 1) * 8 + (lane & 7);   // k-part (trans ldsm)
    const int wC8  = ((lane >> 4) & 1) * 8;                // n-part (trans ldsm)

    for (int t = 0; t < NT_; ++t) {
        if (t + 1 < NT_) { issue(t + 1); CP_WAIT(1); } else { CP_WAIT(0); }
        __syncthreads();

        const uint32_t st = sb + (t & 1) * STAGE_BYTES;
        #pragma unroll
        for (int ks = 0; ks < BK_; ks += 16) {
            uint32_t a[4][4];
            #pragma unroll
            for (int ms = 0; ms < 4; ++ms) {
                uint32_t addr = st + (uint32_t)(wm + ms*16 + aRow) * 80
                              + (uint32_t)(ks + aK8) * 2;
                LDSM_X4(a[ms][0], a[ms][1], a[ms][2], a[ms][3], addr);
            }
            uint32_t bh[4][2];
            #pragma unroll
            for (int np = 0; np < 2; ++np) {
                uint32_t r0, r1, r2, r3;
                uint32_t boff = st + ATILE_ + (uint32_t)(ks + wRow) * BROWB_
                              + (uint32_t)(wn + np*16 + wC8) * 2;
                LDSM_X4T(r0, r1, r2, r3, boff);
                bh[np*2+0][0] = r0; bh[np*2+0][1] = r1;
                bh[np*2+1][0] = r2; bh[np*2+1][1] = r3;
            }
            #pragma unroll
            for (int ms = 0; ms < 4; ++ms)
                #pragma unroll
                for (int ns = 0; ns < 4; ++ns)
                    MMA_F16(d[ms][ns], a[ms], bh[ns]);
        }
        __syncthreads();
    }

    const int g = lane >> 2, q = lane & 3;
    if (mode == 0) {
        __half* Dst = (z == 0) ? g_q16 : (z == 1) ? g_k16 : g_v16;
        const float sc = (z == 0) ? QSCALE_ : 1.0f;
        #pragma unroll
        for (int ns = 0; ns < 4; ++ns) {
            const int col = n0 + wn + ns * 8 + q * 2;
            const float2 bv = *(const float2*)&bias[col];
            #pragma unroll
            for (int ms = 0; ms < 4; ++ms) {
                const int row = m0 + wm + ms * 16 + g;
                __half2 h0 = __floats2half2_rn((d[ms][ns][0] + bv.x) * sc,
                                               (d[ms][ns][1] + bv.y) * sc);
                __half2 h1 = __floats2half2_rn((d[ms][ns][2] + bv.x) * sc,
                                               (d[ms][ns][3] + bv.y) * sc);
                *(uint32_t*)&Dst[(size_t)row * D_ + col]       = *(uint32_t*)&h0;
                *(uint32_t*)&Dst[(size_t)(row + 8) * D_ + col] = *(uint32_t*)&h1;
            }
        }
    } else {
        #pragma unroll
        for (int ns = 0; ns < 4; ++ns) {
            const int col = n0 + wn + ns * 8 + q * 2;
            const float2 bv = *(const float2*)&bias[col];
            #pragma unroll
            for (int ms = 0; ms < 4; ++ms) {
                const int row = m0 + wm + ms * 16 + g;
                float2 v0 = { d[ms][ns][0] + bv.x, d[ms][ns][1] + bv.y };
                float2 v1 = { d[ms][ns][2] + bv.x, d[ms][ns][3] + bv.y };
                *(float2*)&dout[(size_t)row * D_ + col]       = v0;
                *(float2*)&dout[(size_t)(row + 8) * D_ + col] = v1;
            }
        }
    }
}

// ---------------------------------------------------------------------------
// Tensor-core flash attention (UNCHANGED from R15): fp16 single-pass,
// log2-domain softmax, 3-stage {K,V} ring, 2 CTAs/SM.
// ---------------------------------------------------------------------------
#define AROW_ 72
#define ATB_  (64 * AROW_ * 2)        // 9216
#define ASTG_ (2 * ATB_)              // {K, V} = 18432
#define ASMEM_ (3 * ASTG_)            // 55296

__global__ void __launch_bounds__(256, 2) attn_kernel()
{
    const int qb = (int)(gridDim.x - 1 - blockIdx.x);   // heavy tiles first
    const int h  = blockIdx.y;
    const int b  = blockIdx.z;
    const int q0 = qb * 128;
    const size_t hoff = (size_t)h * HD_;

    const int tid  = threadIdx.x;
    const int lane = tid & 31;
    const int wid  = tid >> 5;
    const int g    = lane >> 2;
    const int qd   = lane & 3;

    const uint32_t sb = smem_u32(dsm);

    const int c0 = tid * 2, c1 = tid * 2 + 1;
    const int r0c = c0 >> 3, q0c = c0 & 7;
    const int r1c = c1 >> 3, q1c = c1 & 7;

    // ---- Q (128x64 fp16, pre-scaled) into stage-0 tiles 0,1 (temporary)
    {
        const size_t base0 = (size_t)(b*S_ + q0) * D_ + hoff;
        const size_t base1 = (size_t)(b*S_ + q0 + 64) * D_ + hoff;
        CP_ASYNC16(sb + 0*ATB_ + r0c*144 + q0c*16, g_q16 + base0 + r0c*D_ + q0c*8);
        CP_ASYNC16(sb + 0*ATB_ + r1c*144 + q1c*16, g_q16 + base0 + r1c*D_ + q1c*8);
        CP_ASYNC16(sb + 1*ATB_ + r0c*144 + q0c*16, g_q16 + base1 + r0c*D_ + q0c*8);
        CP_ASYNC16(sb + 1*ATB_ + r1c*144 + q1c*16, g_q16 + base1 + r1c*D_ + q1c*8);
        CP_COMMIT();
    }

    auto issue_tile = [&](int kt) {
        const int stg = (kt + 1) % 3;
        const uint32_t st = sb + stg * ASTG_;
        const size_t base = (size_t)(b*S_ + kt*64) * D_ + hoff;
        const size_t o0 = base + r0c*D_ + q0c*8;
        const size_t o1 = base + r1c*D_ + q1c*8;
        const uint32_t d0 = r0c*144 + q0c*16;
        const uint32_t d1 = r1c*144 + q1c*16;
        CP_ASYNC16(st + 0*ATB_ + d0, g_k16 + o0);
        CP_ASYNC16(st + 0*ATB_ + d1, g_k16 + o1);
        CP_ASYNC16(st + 1*ATB_ + d0, g_v16 + o0);
        CP_ASYNC16(st + 1*ATB_ + d1, g_v16 + o1);
        CP_COMMIT();
    };

    issue_tile(0);          // -> stage 1
    CP_WAIT(1);             // Q group done
    __syncthreads();

    // ---- Q fragments (fp16, 16 regs)
    uint32_t qf[4][4];
    {
        const uint32_t qbase = sb + ((wid < 4) ? 0 : 1) * ATB_;
        const int rr = (wid & 3) * 16 + ((lane >> 3) & 1) * 8 + (lane & 7);
        #pragma unroll
        for (int kat = 0; kat < 4; ++kat) {
            const uint32_t koff = (uint32_t)(kat * 16 + ((lane >> 4) & 1) * 8) * 2;
            LDSM_X4(qf[kat][0], qf[kat][1], qf[kat][2], qf[kat][3],
                    qbase + (uint32_t)rr * 144 + koff);
        }
    }

    float o[8][4];
    #pragma unroll
    for (int j = 0; j < 8; ++j)
        #pragma unroll
        for (int r = 0; r < 4; ++r) o[j][r] = 0.f;
    float mrow0 = -1e30f, mrow1 = -1e30f, lrow0 = 0.f, lrow1 = 0.f;

    const int wrow0 = q0 + wid * 16;

    const int kRow = ((lane >> 4) & 1) * 8 + (lane & 7);
    const int kK8  = ((lane >> 3) & 1) * 8;
    const int vRow = ((lane >> 3) & 1) * 8 + (lane & 7);
    const int vC8  = ((lane >> 4) & 1) * 8;

    const int nkt = 2 * (qb + 1);
    for (int kt = 0; kt < nkt; ++kt) {
        const int k0 = kt * 64;
        if (kt + 1 < nkt) { issue_tile(kt + 1); CP_WAIT(1); } else { CP_WAIT(0); }
        __syncthreads();

        const uint32_t st = sb + ((kt + 1) % 3) * ASTG_;
        const uint32_t uK = st, uV = st + ATB_;

        if (k0 <= wrow0 + 15) {
            // ---- S = Q*K (single pass; scores already in log2 domain)
            float s[8][4];
            #pragma unroll
            for (int j = 0; j < 8; ++j)
                #pragma unroll
                for (int r = 0; r < 4; ++r) s[j][r] = 0.f;

            #pragma unroll
            for (int kat = 0; kat < 4; ++kat) {
                uint32_t kh[4][4];
                #pragma unroll
                for (int jp = 0; jp < 4; ++jp) {
                    const uint32_t roff = (uint32_t)(jp*16 + kRow) * 144
                                        + (uint32_t)(kat*16 + kK8) * 2;
                    LDSM_X4(kh[jp][0], kh[jp][1], kh[jp][2], kh[jp][3], uK + roff);
                }
                #pragma unroll
                for (int jp = 0; jp < 4; ++jp) {
                    MMA_F16(s[jp*2+0], qf[kat], (&kh[jp][0]));
                    MMA_F16(s[jp*2+1], qf[kat], (&kh[jp][2]));
                }
            }

            // ---- online softmax (log2 domain)
            const int row0 = wrow0 + g;
            const int row1 = row0 + 8;
            const bool needmask = (k0 + 63 > wrow0);
            float nm0 = mrow0, nm1 = mrow1;
            #pragma unroll
            for (int j = 0; j < 8; ++j) {
                const int col = k0 + j*8 + qd*2;
                float v0 = s[j][0], v1 = s[j][1];
                float v2 = s[j][2], v3 = s[j][3];
                if (needmask) {
                    if (col + 0 > row0) v0 = -1e30f;
                    if (col + 1 > row0) v1 = -1e30f;
                    if (col + 0 > row1) v2 = -1e30f;
                    if (col + 1 > row1) v3 = -1e30f;
                }
                s[j][0] = v0; s[j][1] = v1; s[j][2] = v2; s[j][3] = v3;
                nm0 = fmaxf(nm0, fmaxf(v0, v1));
                nm1 = fmaxf(nm1, fmaxf(v2, v3));
            }
            nm0 = fmaxf(nm0, __shfl_xor_sync(0xffffffffu, nm0, 1));
            nm0 = fmaxf(nm0, __shfl_xor_sync(0xffffffffu, nm0, 2));
            nm1 = fmaxf(nm1, __shfl_xor_sync(0xffffffffu, nm1, 1));
            nm1 = fmaxf(nm1, __shfl_xor_sync(0xffffffffu, nm1, 2));

            const float alpha0 = exp2f(mrow0 - nm0);
            const float alpha1 = exp2f(mrow1 - nm1);
            mrow0 = nm0; mrow1 = nm1;

            uint32_t pf[4][4];
            float ps0 = 0.f, ps1 = 0.f;
            #pragma unroll
            for (int jp = 0; jp < 4; ++jp) {
                #pragma unroll
                for (int half = 0; half < 2; ++half) {
                    const int j = jp*2 + half;
                    const float p0 = exp2f(s[j][0] - nm0);
                    const float p1 = exp2f(s[j][1] - nm0);
                    const float p2 = exp2f(s[j][2] - nm1);
                    const float p3 = exp2f(s[j][3] - nm1);
                    ps0 += p0 + p1; ps1 += p2 + p3;
                    __half2 h01 = __floats2half2_rn(p0, p1);
                    __half2 h23 = __floats2half2_rn(p2, p3);
                    pf[jp][0 + half*2] = *(uint32_t*)&h01;
                    pf[jp][1 + half*2] = *(uint32_t*)&h23;
                }
            }
            ps0 += __shfl_xor_sync(0xffffffffu, ps0, 1);
            ps0 += __shfl_xor_sync(0xffffffffu, ps0, 2);
            ps1 += __shfl_xor_sync(0xffffffffu, ps1, 1);
            ps1 += __shfl_xor_sync(0xffffffffu, ps1, 2);
            lrow0 = lrow0 * alpha0 + ps0;
            lrow1 = lrow1 * alpha1 + ps1;
            #pragma unroll
            for (int j = 0; j < 8; ++j) {
                o[j][0] *= alpha0; o[j][1] *= alpha0;
                o[j][2] *= alpha1; o[j][3] *= alpha1;
            }

            // ---- O += P*V (single pass)
            #pragma unroll
            for (int kat = 0; kat < 4; ++kat) {
                uint32_t vh[4][4];
                #pragma unroll
                for (int jp = 0; jp < 4; ++jp) {
                    const uint32_t roff = (uint32_t)(kat*16 + vRow) * 144
                                        + (uint32_t)(jp*16 + vC8) * 2;
                    LDSM_X4T(vh[jp][0], vh[jp][1], vh[jp][2], vh[jp][3], uV + roff);
                }
                #pragma unroll
                for (int jp = 0; jp < 4; ++jp) {
                    MMA_F16(o[jp*2+0], pf[kat], (&vh[jp][0]));
                    MMA_F16(o[jp*2+1], pf[kat], (&vh[jp][2]));
                }
            }
        }
    }

    // ---- normalize + write fp16 [B,S,D]
    const float inv0 = 1.f / lrow0;
    const float inv1 = 1.f / lrow1;
    const int row0 = q0 + wid*16 + g;
    #pragma unroll
    for (int j = 0; j < 8; ++j) {
        const int col = j*8 + qd*2;
        __half2 v0 = __floats2half2_rn(o[j][0] * inv0, o[j][1] * inv0);
        __half2 v1 = __floats2half2_rn(o[j][2] * inv1, o[j][3] * inv1);
        *(uint32_t*)&g_oh16[(size_t)(b*S_ + row0) * D_ + hoff + col]     = *(uint32_t*)&v0;
        *(uint32_t*)&g_oh16[(size_t)(b*S_ + row0 + 8) * D_ + hoff + col] = *(uint32_t*)&v1;
    }
}

// ---------------------------------------------------------------------------
extern "C" void kernel_launch(void* const* d_in, const int* in_sizes, int n_in,
                              void* d_out, int out_size)
{
    (void)in_sizes; (void)n_in; (void)out_size;
    const float* x  = (const float*)d_in[0];
    const float* Wq = (const float*)d_in[1];
    const float* bq = (const float*)d_in[2];
    const float* Wk = (const float*)d_in[3];
    const float* bk = (const float*)d_in[4];
    const float* Wv = (const float*)d_in[5];
    const float* bv = (const float*)d_in[6];
    const float* Wo = (const float*)d_in[7];
    const float* bo = (const float*)d_in[8];
    float* out = (float*)d_out;

    cudaFuncSetAttribute(mma_gemm, cudaFuncAttributeMaxDynamicSharedMemorySize, GSMEM_BYTES);
    cudaFuncSetAttribute(attn_kernel, cudaFuncAttributeMaxDynamicSharedMemorySize, ASMEM_);

    convert_h<<<(M_*D_/4 + 255)/256, 256>>>((const float4*)x);
    dim3 wg(D_*D_/4/256, 4);
    convert_w<<<wg, 256>>>(Wq, Wk, Wv, Wo);

    dim3 gq(D_/128, M_/128, 3);
    mma_gemm<<<gq, 256, GSMEM_BYTES>>>(0, bq, bk, bv, nullptr);

    dim3 ga(S_/128, H_, B_);
    attn_kernel<<<ga, 256, ASMEM_>>>();

    dim3 go(D_/128, M_/128, 1);
    mma_gemm<<<go, 256, GSMEM_BYTES>>>(1, bo, nullptr, nullptr, out);
}